// round 2
// baseline (speedup 1.0000x reference)
#include <cuda_runtime.h>
#include <cuda_bf16.h>
#include <math.h>

#define TT 4096
#define DD 1024
#define NH 16
#define HDIM 64

// Scratch (allocation-free rule: device globals)
__device__ float g_qkv[(size_t)TT * 3 * DD];   // 48 MB: per-row [q(1024) | k(1024) | v(1024)]
__device__ float g_att[(size_t)TT * DD];       // 16 MB: attention output, (T, H*HD) layout

__device__ __forceinline__ float fast_exp2(float x) {
    float y;
    asm("ex2.approx.ftz.f32 %0, %1;" : "=f"(y) : "f"(x));
    return y;
}

// ---------------------------------------------------------------------------
// C[M,N] = A[M,K] @ B[K,N], all row-major. Requires M%128==0, N%128==0, K%8==0.
// 128x128 block tile, BK=8, 8x8 per-thread tile, 256 threads. (unchanged)
// ---------------------------------------------------------------------------
__global__ __launch_bounds__(256) void sgemm_kernel(
    const float* __restrict__ A, const float* __restrict__ B,
    float* __restrict__ C, int M, int N, int K)
{
    const int BK = 8;
    __shared__ float As[BK][128];   // transposed A tile: As[k][m]
    __shared__ float Bs[BK][128];

    const int tid = threadIdx.x;
    const int bm = blockIdx.y * 128;
    const int bn = blockIdx.x * 128;
    const int tr = (tid / 16) * 8;
    const int tc = (tid % 16) * 8;

    const int arow = tid >> 1;
    const int acol = (tid & 1) * 4;
    const int brow = tid >> 5;
    const int bcol = (tid & 31) * 4;

    float acc[8][8];
    #pragma unroll
    for (int i = 0; i < 8; i++)
        #pragma unroll
        for (int j = 0; j < 8; j++) acc[i][j] = 0.f;

    const float* Aptr = A + (size_t)(bm + arow) * K + acol;
    const float* Bptr = B + (size_t)brow * N + bn + bcol;

    for (int k0 = 0; k0 < K; k0 += BK) {
        float4 av = *(const float4*)(Aptr + k0);
        float4 bv = *(const float4*)(Bptr + (size_t)k0 * N);
        As[acol + 0][arow] = av.x;
        As[acol + 1][arow] = av.y;
        As[acol + 2][arow] = av.z;
        As[acol + 3][arow] = av.w;
        *(float4*)&Bs[brow][bcol] = bv;
        __syncthreads();

        #pragma unroll
        for (int k = 0; k < BK; k++) {
            float ra[8], rb[8];
            #pragma unroll
            for (int i = 0; i < 8; i++) ra[i] = As[k][tr + i];
            #pragma unroll
            for (int j = 0; j < 8; j++) rb[j] = Bs[k][tc + j];
            #pragma unroll
            for (int i = 0; i < 8; i++)
                #pragma unroll
                for (int j = 0; j < 8; j++)
                    acc[i][j] = fmaf(ra[i], rb[j], acc[i][j]);
        }
        __syncthreads();
    }

    #pragma unroll
    for (int i = 0; i < 8; i++) {
        float* cp = C + (size_t)(bm + tr + i) * N + bn + tc;
        *(float4*)(cp)     = make_float4(acc[i][0], acc[i][1], acc[i][2], acc[i][3]);
        *(float4*)(cp + 4) = make_float4(acc[i][4], acc[i][5], acc[i][6], acc[i][7]);
    }
}

// ---------------------------------------------------------------------------
// Causal flash attention, fp32, 4 lanes per query.
// Block = 256 threads = 64 queries of one head. Each query is handled by a
// lane-aligned group of 4 threads; each lane owns a 16-dim slice of q/acc.
// Partial q.k dots are reduced with 2x shfl.xor. Online softmax state (m,l)
// is replicated (identically computed) across the 4 lanes.
// Registers/thread ~60 (vs ~230 before) -> much higher occupancy.
// ---------------------------------------------------------------------------
__global__ __launch_bounds__(256) void attn_kernel(
    const float* __restrict__ qkv, float* __restrict__ out)
{
    const int h   = blockIdx.y;
    const int q0  = blockIdx.x * 64;
    const int tid = threadIdx.x;
    const int qi  = tid >> 2;         // query within block (0..63)
    const int sl  = (tid & 3) * 16;   // dim-slice start (0,16,32,48)
    const int r   = q0 + qi;          // global query row

    __shared__ float Ks[64][HDIM];
    __shared__ float Vs[64][HDIM];

    // q scaled by (1/sqrt(HD)) * log2(e): scores come out in log2 units
    const float sc = 0.125f * 1.4426950408889634f;
    float q[16];
    {
        const float* qp = qkv + (size_t)r * (3 * DD) + h * HDIM + sl;
        #pragma unroll
        for (int d4 = 0; d4 < 4; d4++) {
            float4 v = *(const float4*)(qp + d4 * 4);
            q[d4 * 4 + 0] = v.x * sc;
            q[d4 * 4 + 1] = v.y * sc;
            q[d4 * 4 + 2] = v.z * sc;
            q[d4 * 4 + 3] = v.w * sc;
        }
    }

    float m = -INFINITY, l = 0.f;
    float acc[16];
    #pragma unroll
    for (int d = 0; d < 16; d++) acc[d] = 0.f;

    const int kend = q0 + 64;   // causal bound covering every query in block

    for (int k0 = 0; k0 < kend; k0 += 64) {
        // cooperative tile load: 64 keys x 64 dims of K and V
        // 64*16 = 1024 float4 slots per tile, 256 threads -> 4 each
        #pragma unroll
        for (int it = 0; it < 4; it++) {
            int i   = tid + it * 256;
            int row = i >> 4;
            int c4  = (i & 15) * 4;
            const float* kp = qkv + (size_t)(k0 + row) * (3 * DD) + DD + h * HDIM + c4;
            *(float4*)&Ks[row][c4] = *(const float4*)kp;
            *(float4*)&Vs[row][c4] = *(const float4*)(kp + DD);
        }
        __syncthreads();

        #pragma unroll
        for (int jc = 0; jc < 64; jc += 8) {
            float s[8];
            float cmax = m;
            #pragma unroll
            for (int jj = 0; jj < 8; jj++) {
                const int key = k0 + jc + jj;
                float sj = 0.f;
                const float4* kr = (const float4*)(&Ks[jc + jj][sl]);
                #pragma unroll
                for (int d4 = 0; d4 < 4; d4++) {
                    float4 kv = kr[d4];
                    sj = fmaf(q[d4 * 4 + 0], kv.x, sj);
                    sj = fmaf(q[d4 * 4 + 1], kv.y, sj);
                    sj = fmaf(q[d4 * 4 + 2], kv.z, sj);
                    sj = fmaf(q[d4 * 4 + 3], kv.w, sj);
                }
                // reduce partial dot across the 4-lane group
                sj += __shfl_xor_sync(0xffffffffu, sj, 1);
                sj += __shfl_xor_sync(0xffffffffu, sj, 2);
                sj = (key <= r) ? sj : -INFINITY;
                s[jj] = sj;
                cmax = fmaxf(cmax, sj);
            }
            // chunk rescale (cmax >= m; key 0 of tile 0 is always valid so m
            // becomes finite on the very first chunk; cmax-m never NaN)
            float c = fast_exp2(m - cmax);
            m = cmax;
            l *= c;
            #pragma unroll
            for (int d = 0; d < 16; d++) acc[d] *= c;
            #pragma unroll
            for (int jj = 0; jj < 8; jj++) {
                float p = fast_exp2(s[jj] - m);   // masked: exp2(-inf)=0
                l += p;
                const float4* vr = (const float4*)(&Vs[jc + jj][sl]);
                #pragma unroll
                for (int d4 = 0; d4 < 4; d4++) {
                    float4 vv = vr[d4];
                    acc[d4 * 4 + 0] = fmaf(p, vv.x, acc[d4 * 4 + 0]);
                    acc[d4 * 4 + 1] = fmaf(p, vv.y, acc[d4 * 4 + 1]);
                    acc[d4 * 4 + 2] = fmaf(p, vv.z, acc[d4 * 4 + 2]);
                    acc[d4 * 4 + 3] = fmaf(p, vv.w, acc[d4 * 4 + 3]);
                }
            }
        }
        __syncthreads();
    }

    const float inv_l = 1.0f / l;     // identical across the 4 lanes
    float* op = out + (size_t)r * DD + h * HDIM + sl;
    #pragma unroll
    for (int d4 = 0; d4 < 4; d4++) {
        float4 v;
        v.x = acc[d4 * 4 + 0] * inv_l;
        v.y = acc[d4 * 4 + 1] * inv_l;
        v.z = acc[d4 * 4 + 2] * inv_l;
        v.w = acc[d4 * 4 + 3] * inv_l;
        *(float4*)(op + d4 * 4) = v;
    }
}

// ---------------------------------------------------------------------------
extern "C" void kernel_launch(void* const* d_in, const int* in_sizes, int n_in,
                              void* d_out, int out_size)
{
    const float* x    = (const float*)d_in[0];
    const float* wqkv = (const float*)d_in[1];
    const float* wout = (const float*)d_in[2];
    float* out = (float*)d_out;

    float* qkv = nullptr;
    float* att = nullptr;
    cudaGetSymbolAddress((void**)&qkv, g_qkv);
    cudaGetSymbolAddress((void**)&att, g_att);

    // 1) QKV projection: (4096x1024) @ (1024x3072)
    dim3 g1(3 * DD / 128, TT / 128);
    sgemm_kernel<<<g1, 256>>>(x, wqkv, qkv, TT, 3 * DD, DD);

    // 2) causal attention per head (64 queries per block, 4 lanes per query)
    dim3 g2(TT / 64, NH);
    attn_kernel<<<g2, 256>>>(qkv, att);

    // 3) output projection: (4096x1024) @ (1024x1024)
    dim3 g3(DD / 128, TT / 128);
    sgemm_kernel<<<g3, 256>>>(att, wout, out, TT, DD, DD);
}

// round 4
// speedup vs baseline: 2.7776x; 2.7776x over previous
#include <cuda_runtime.h>
#include <cuda_bf16.h>
#include <math.h>

#define TT 4096
#define DD 1024
#define NH 16
#define HDIM 64

// Scratch (allocation-free rule: device globals)
__device__ float g_qkv[(size_t)TT * 3 * DD];   // 48 MB: per-row [q(1024) | k(1024) | v(1024)]
__device__ float g_att[(size_t)TT * DD];       // 16 MB: attention output, (T, H*HD) layout

__device__ __forceinline__ float fast_exp2(float x) {
    float y;
    asm("ex2.approx.ftz.f32 %0, %1;" : "=f"(y) : "f"(x));
    return y;
}

// ---------------------------------------------------------------------------
// C[M,N] = A[M,K] @ B[K,N], all row-major. Requires M%128==0, N%128==0, K%8==0.
// 128x128 block tile, BK=8, 8x8 per-thread tile, 256 threads. (unchanged)
// ---------------------------------------------------------------------------
__global__ __launch_bounds__(256) void sgemm_kernel(
    const float* __restrict__ A, const float* __restrict__ B,
    float* __restrict__ C, int M, int N, int K)
{
    const int BK = 8;
    __shared__ float As[BK][128];   // transposed A tile: As[k][m]
    __shared__ float Bs[BK][128];

    const int tid = threadIdx.x;
    const int bm = blockIdx.y * 128;
    const int bn = blockIdx.x * 128;
    const int tr = (tid / 16) * 8;
    const int tc = (tid % 16) * 8;

    const int arow = tid >> 1;
    const int acol = (tid & 1) * 4;
    const int brow = tid >> 5;
    const int bcol = (tid & 31) * 4;

    float acc[8][8];
    #pragma unroll
    for (int i = 0; i < 8; i++)
        #pragma unroll
        for (int j = 0; j < 8; j++) acc[i][j] = 0.f;

    const float* Aptr = A + (size_t)(bm + arow) * K + acol;
    const float* Bptr = B + (size_t)brow * N + bn + bcol;

    for (int k0 = 0; k0 < K; k0 += BK) {
        float4 av = *(const float4*)(Aptr + k0);
        float4 bv = *(const float4*)(Bptr + (size_t)k0 * N);
        As[acol + 0][arow] = av.x;
        As[acol + 1][arow] = av.y;
        As[acol + 2][arow] = av.z;
        As[acol + 3][arow] = av.w;
        *(float4*)&Bs[brow][bcol] = bv;
        __syncthreads();

        #pragma unroll
        for (int k = 0; k < BK; k++) {
            float ra[8], rb[8];
            #pragma unroll
            for (int i = 0; i < 8; i++) ra[i] = As[k][tr + i];
            #pragma unroll
            for (int j = 0; j < 8; j++) rb[j] = Bs[k][tc + j];
            #pragma unroll
            for (int i = 0; i < 8; i++)
                #pragma unroll
                for (int j = 0; j < 8; j++)
                    acc[i][j] = fmaf(ra[i], rb[j], acc[i][j]);
        }
        __syncthreads();
    }

    #pragma unroll
    for (int i = 0; i < 8; i++) {
        float* cp = C + (size_t)(bm + tr + i) * N + bn + tc;
        *(float4*)(cp)     = make_float4(acc[i][0], acc[i][1], acc[i][2], acc[i][3]);
        *(float4*)(cp + 4) = make_float4(acc[i][4], acc[i][5], acc[i][6], acc[i][7]);
    }
}

// ---------------------------------------------------------------------------
// Causal flash attention, fp32, GEMM-tiled.
// Block = 128 queries of one head, 256 threads (8 warps).
// Per 64-key tile:
//   GEMM1: S(128x64) = Q(128x64) @ K^T  — 4x8 microtile per thread
//   smem softmax: row max/sum via partial arrays (no shuffles)
//   GEMM2: O(128x64) += P(128x64) @ V   — same microtile, O in registers
// Thread map: warp cg=tid>>5 owns cols [cg*8, cg*8+8); rg=tid&31 owns rows
// [rg*4, rg*4+4). B-operand smem loads are warp-uniform (broadcast),
// A-operand float4 loads are conflict-free.
// ---------------------------------------------------------------------------
__global__ __launch_bounds__(256) void attn_kernel(
    const float* __restrict__ qkv, float* __restrict__ out)
{
    extern __shared__ float sm[];
    float* Qs   = sm;                    // [64][128] d-major (transposed)
    float* Ks   = Qs + 64 * 128;         // [64][64]  d-major (transposed)
    float* Vs   = Ks + 64 * 64;          // [64][64]  key-major
    float* Pt   = Vs + 64 * 64;          // [64][128] key-major (P transposed)
    float* mrow = Pt + 64 * 128;         // [128] running max (log2 units)
    float* lrow = mrow + 128;            // [128] running denom
    float* pmax = lrow + 128;            // [128][9] partial max (padded)
    float* psum = pmax + 128 * 9;        // [128][9] partial sum (padded)

    const int h   = blockIdx.y;
    const int bx  = (gridDim.x - 1) - blockIdx.x;   // heavy blocks first
    const int q0  = bx * 128;
    const int tid = threadIdx.x;
    const int cg  = tid >> 5;            // warp id: column group
    const int rg  = tid & 31;            // row group
    const int r0  = rg * 4;
    const int c0  = cg * 8;

    const float sc = 0.125f * 1.4426950408889634f;  // 1/sqrt(64) * log2(e)

    // Load Q tile (scaled) transposed into Qs[d][row]
    #pragma unroll
    for (int it = 0; it < 8; it++) {
        int idx = it * 256 + tid;            // 0..2047
        int row = idx >> 4;                  // 0..127
        int f4  = (idx & 15) * 4;            // d base
        const float* qp = qkv + (size_t)(q0 + row) * (3 * DD) + h * HDIM + f4;
        float4 v = *(const float4*)qp;
        Qs[(f4 + 0) * 128 + row] = v.x * sc;
        Qs[(f4 + 1) * 128 + row] = v.y * sc;
        Qs[(f4 + 2) * 128 + row] = v.z * sc;
        Qs[(f4 + 3) * 128 + row] = v.w * sc;
    }
    if (tid < 128) { mrow[tid] = -INFINITY; lrow[tid] = 0.f; }

    float accO[4][8];
    #pragma unroll
    for (int i = 0; i < 4; i++)
        #pragma unroll
        for (int j = 0; j < 8; j++) accO[i][j] = 0.f;

    const int ntiles = (q0 + 128) >> 6;
    for (int t = 0; t < ntiles; t++) {
        const int k0 = t << 6;
        __syncthreads();   // (A) Ks/Vs/Pt free for reuse

        // Load K transposed: Ks[d][key]. key = tid>>2, 4 float4 columns/thread.
        {
            int key = tid >> 2;
            const float* kp = qkv + (size_t)(k0 + key) * (3 * DD) + DD + h * HDIM;
            #pragma unroll
            for (int it = 0; it < 4; it++) {
                int f4 = ((tid & 3) + it * 4) * 4;
                float4 v = *(const float4*)(kp + f4);
                Ks[(f4 + 0) * 64 + key] = v.x;
                Ks[(f4 + 1) * 64 + key] = v.y;
                Ks[(f4 + 2) * 64 + key] = v.z;
                Ks[(f4 + 3) * 64 + key] = v.w;
            }
        }
        // Load V as-is: Vs[key][d]
        #pragma unroll
        for (int it = 0; it < 4; it++) {
            int idx = it * 256 + tid;          // 0..1023
            int key = idx >> 4;
            int f4  = (idx & 15) * 4;
            const float* vp = qkv + (size_t)(k0 + key) * (3 * DD) + 2 * DD + h * HDIM + f4;
            *(float4*)&Vs[key * 64 + f4] = *(const float4*)vp;
        }
        __syncthreads();   // (B) tiles ready

        // GEMM1: S = Q @ K^T  (scores already in log2 units via sc)
        float s[4][8];
        #pragma unroll
        for (int i = 0; i < 4; i++)
            #pragma unroll
            for (int j = 0; j < 8; j++) s[i][j] = 0.f;

        #pragma unroll 16
        for (int d = 0; d < 64; d++) {
            float4 qa = *(const float4*)&Qs[d * 128 + r0];
            float4 b0 = *(const float4*)&Ks[d * 64 + c0];
            float4 b1 = *(const float4*)&Ks[d * 64 + c0 + 4];
            float aa[4] = {qa.x, qa.y, qa.z, qa.w};
            float bb[8] = {b0.x, b0.y, b0.z, b0.w, b1.x, b1.y, b1.z, b1.w};
            #pragma unroll
            for (int i = 0; i < 4; i++)
                #pragma unroll
                for (int j = 0; j < 8; j++)
                    s[i][j] = fmaf(aa[i], bb[j], s[i][j]);
        }

        // Causal mask: only the last two tiles can contain masked pairs
        if (k0 + 64 > q0) {
            #pragma unroll
            for (int i = 0; i < 4; i++)
                #pragma unroll
                for (int j = 0; j < 8; j++)
                    if (k0 + c0 + j > q0 + r0 + i) s[i][j] = -INFINITY;
        }

        // partial row max
        #pragma unroll
        for (int i = 0; i < 4; i++) {
            float pm = s[i][0];
            #pragma unroll
            for (int j = 1; j < 8; j++) pm = fmaxf(pm, s[i][j]);
            pmax[(r0 + i) * 9 + cg] = pm;
        }
        __syncthreads();   // (C) pmax ready

        // full row max (replicated per cg, identical), p = exp2(s - m_new),
        // partial sums, P transposed to smem
        float cf[4];
        #pragma unroll
        for (int i = 0; i < 4; i++) {
            int row = r0 + i;
            float mold = mrow[row];
            float mx = mold;
            #pragma unroll
            for (int g = 0; g < 8; g++) mx = fmaxf(mx, pmax[row * 9 + g]);
            cf[i] = fast_exp2(mold - mx);      // tile 0: exp2(-inf)=0, harmless
            float ps = 0.f;
            #pragma unroll
            for (int j = 0; j < 8; j++) {
                float p = fast_exp2(s[i][j] - mx);   // masked: 0
                ps += p;
                Pt[(c0 + j) * 128 + row] = p;
            }
            psum[row * 9 + cg] = ps;
        }
        __syncthreads();   // (D) psum/Pt ready; mrow reads done

        // stats update, one thread per row
        if (tid < 128) {
            int row = tid;
            float mold = mrow[row];
            float mx = mold;
            #pragma unroll
            for (int g = 0; g < 8; g++) mx = fmaxf(mx, pmax[row * 9 + g]);
            float c = fast_exp2(mold - mx);
            float sum = 0.f;
            #pragma unroll
            for (int g = 0; g < 8; g++) sum += psum[row * 9 + g];
            lrow[row] = lrow[row] * c + sum;
            mrow[row] = mx;
        }
        __syncthreads();   // (E) stats committed

        // O rescale + GEMM2: O += P @ V
        #pragma unroll
        for (int i = 0; i < 4; i++) {
            float c = cf[i];
            #pragma unroll
            for (int j = 0; j < 8; j++) accO[i][j] *= c;
        }
        #pragma unroll 16
        for (int k = 0; k < 64; k++) {
            float4 pa = *(const float4*)&Pt[k * 128 + r0];
            float4 v0 = *(const float4*)&Vs[k * 64 + c0];
            float4 v1 = *(const float4*)&Vs[k * 64 + c0 + 4];
            float aa[4] = {pa.x, pa.y, pa.z, pa.w};
            float bb[8] = {v0.x, v0.y, v0.z, v0.w, v1.x, v1.y, v1.z, v1.w};
            #pragma unroll
            for (int i = 0; i < 4; i++)
                #pragma unroll
                for (int j = 0; j < 8; j++)
                    accO[i][j] = fmaf(aa[i], bb[j], accO[i][j]);
        }
    }

    // epilogue: divide by l, write (T, H*HD)
    #pragma unroll
    for (int i = 0; i < 4; i++) {
        int row = q0 + r0 + i;
        float inv = 1.0f / lrow[r0 + i];
        float4 o0, o1;
        o0.x = accO[i][0] * inv; o0.y = accO[i][1] * inv;
        o0.z = accO[i][2] * inv; o0.w = accO[i][3] * inv;
        o1.x = accO[i][4] * inv; o1.y = accO[i][5] * inv;
        o1.z = accO[i][6] * inv; o1.w = accO[i][7] * inv;
        float* op = out + (size_t)row * DD + h * HDIM + c0;
        *(float4*)op       = o0;
        *(float4*)(op + 4) = o1;
    }
}

static const int ATTN_SMEM = (64 * 128 + 64 * 64 + 64 * 64 + 64 * 128 + 128 + 128 + 128 * 9 + 128 * 9) * 4;

// ---------------------------------------------------------------------------
extern "C" void kernel_launch(void* const* d_in, const int* in_sizes, int n_in,
                              void* d_out, int out_size)
{
    const float* x    = (const float*)d_in[0];
    const float* wqkv = (const float*)d_in[1];
    const float* wout = (const float*)d_in[2];
    float* out = (float*)d_out;

    float* qkv = nullptr;
    float* att = nullptr;
    cudaGetSymbolAddress((void**)&qkv, g_qkv);
    cudaGetSymbolAddress((void**)&att, g_att);

    cudaFuncSetAttribute(attn_kernel, cudaFuncAttributeMaxDynamicSharedMemorySize, ATTN_SMEM);

    // 1) QKV projection: (4096x1024) @ (1024x3072)
    dim3 g1(3 * DD / 128, TT / 128);
    sgemm_kernel<<<g1, 256>>>(x, wqkv, qkv, TT, 3 * DD, DD);

    // 2) causal attention, GEMM-tiled, 128 queries/block
    dim3 g2(TT / 128, NH);
    attn_kernel<<<g2, 256, ATTN_SMEM>>>(qkv, att);

    // 3) output projection: (4096x1024) @ (1024x1024)
    dim3 g3(DD / 128, TT / 128);
    sgemm_kernel<<<g3, 256>>>(att, wout, out, TT, DD, DD);
}

// round 8
// speedup vs baseline: 3.5423x; 1.2753x over previous
#include <cuda_runtime.h>
#include <cuda_bf16.h>
#include <math.h>
#include <stdint.h>

#define TT 4096
#define DD 1024
#define NH 16
#define HDIM 64

// ---------------------------------------------------------------------------
// Scratch (allocation-free rule: device globals). 16B-aligned.
// ---------------------------------------------------------------------------
__device__ __align__(16) float g_qkv[(size_t)TT * 3 * DD];   // 48 MB
__device__ __align__(16) float g_att[(size_t)TT * DD];       // 16 MB
__device__ __align__(16) __nv_bfloat16 g_xhi[(size_t)TT * DD],      g_xlo[(size_t)TT * DD];
__device__ __align__(16) __nv_bfloat16 g_w1hi[(size_t)3 * DD * DD], g_w1lo[(size_t)3 * DD * DD];
__device__ __align__(16) __nv_bfloat16 g_w2hi[(size_t)DD * DD],     g_w2lo[(size_t)DD * DD];
__device__ __align__(16) __nv_bfloat16 g_ahi[(size_t)TT * DD],      g_alo[(size_t)TT * DD];

// ---------------------------------------------------------------------------
// PTX helpers (sm_80-era: ldmatrix / mma.sync / cp.async — valid on compute_100)
// ---------------------------------------------------------------------------
__device__ __forceinline__ uint32_t smem_u32(const void* p) {
    uint32_t a;
    asm("{ .reg .u64 t; cvta.to.shared.u64 t, %1; cvt.u32.u64 %0, t; }" : "=r"(a) : "l"(p));
    return a;
}
__device__ __forceinline__ void ldsm_x4(uint32_t& r0, uint32_t& r1, uint32_t& r2, uint32_t& r3,
                                        uint32_t addr) {
    asm volatile("ldmatrix.sync.aligned.m8n8.x4.shared.b16 {%0,%1,%2,%3}, [%4];"
                 : "=r"(r0), "=r"(r1), "=r"(r2), "=r"(r3) : "r"(addr));
}
__device__ __forceinline__ void mma16816(float& c0, float& c1, float& c2, float& c3,
                                         uint32_t a0, uint32_t a1, uint32_t a2, uint32_t a3,
                                         uint32_t b0, uint32_t b1) {
    asm volatile("mma.sync.aligned.m16n8k16.row.col.f32.bf16.bf16.f32 "
                 "{%0,%1,%2,%3}, {%4,%5,%6,%7}, {%8,%9}, {%0,%1,%2,%3};"
                 : "+f"(c0), "+f"(c1), "+f"(c2), "+f"(c3)
                 : "r"(a0), "r"(a1), "r"(a2), "r"(a3), "r"(b0), "r"(b1));
}
__device__ __forceinline__ void cp16(uint32_t dst, const void* src) {
    asm volatile("cp.async.cg.shared.global [%0], [%1], 16;" :: "r"(dst), "l"(src) : "memory");
}
__device__ __forceinline__ void cp_commit() { asm volatile("cp.async.commit_group;" ::: "memory"); }
template <int N> __device__ __forceinline__ void cp_wait() {
    asm volatile("cp.async.wait_group %0;" :: "n"(N) : "memory");
}
__device__ __forceinline__ float fast_exp2(float x) {
    float y;
    asm("ex2.approx.ftz.f32 %0, %1;" : "=f"(y) : "f"(x));
    return y;
}
// pack two fp32 into one u32 of (bf16 lo | bf16 hi) WITHOUT address-taken locals
__device__ __forceinline__ uint32_t pack_bf16x2(float a, float b) {
    __nv_bfloat162 t = __floats2bfloat162_rn(a, b);
    return *reinterpret_cast<uint32_t*>(&t);   // __nv_bfloat162 is 4B-aligned
}

// ---------------------------------------------------------------------------
// fp32 -> (hi, lo) bf16 split, elementwise. n % 4 == 0. Register-only packing.
// ---------------------------------------------------------------------------
__global__ void split_convert(const float* __restrict__ s,
                              __nv_bfloat16* __restrict__ hi,
                              __nv_bfloat16* __restrict__ lo, int n)
{
    int i = (blockIdx.x * blockDim.x + threadIdx.x) * 4;
    if (i >= n) return;
    float4 v = *(const float4*)(s + i);
    float h0 = __bfloat162float(__float2bfloat16(v.x));
    float h1 = __bfloat162float(__float2bfloat16(v.y));
    float h2 = __bfloat162float(__float2bfloat16(v.z));
    float h3 = __bfloat162float(__float2bfloat16(v.w));
    uint2 hh, ll;
    hh.x = pack_bf16x2(h0, h1);
    hh.y = pack_bf16x2(h2, h3);
    ll.x = pack_bf16x2(v.x - h0, v.y - h1);
    ll.y = pack_bf16x2(v.z - h2, v.w - h3);
    *(uint2*)(hi + i) = hh;   // g_* arrays are 16B aligned, i % 4 == 0
    *(uint2*)(lo + i) = ll;
}

// ---------------------------------------------------------------------------
// w[K][N] fp32 -> wT hi/lo [N][K] bf16 (transpose + split). block (32,8).
// Scalar bf16 stores only (no punning).
// ---------------------------------------------------------------------------
__global__ void transpose_convert(const float* __restrict__ w,
                                  __nv_bfloat16* __restrict__ hi,
                                  __nv_bfloat16* __restrict__ lo, int K, int N)
{
    __shared__ float t[32][33];
    int n0 = blockIdx.x * 32, k0 = blockIdx.y * 32;
    int tx = threadIdx.x, ty = threadIdx.y;
    for (int j = ty; j < 32; j += 8)
        t[j][tx] = w[(size_t)(k0 + j) * N + n0 + tx];
    __syncthreads();
    for (int j = ty; j < 32; j += 8) {
        float v = t[tx][j];
        __nv_bfloat16 h = __float2bfloat16(v);
        __nv_bfloat16 l = __float2bfloat16(v - __bfloat162float(h));
        size_t o = (size_t)(n0 + j) * K + k0 + tx;
        hi[o] = h; lo[o] = l;
    }
}

// ---------------------------------------------------------------------------
// mma.sync bf16 split GEMM: C[M,N] fp32 = A @ B^T
//   A as Ah/Al [M][K] bf16, B as Bh/Bl [N][K] bf16 (both K contiguous)
//   C ~= Ah*Bh + Ah*Bl + Al*Bh
// CTA 128x128, 256 threads = 8 warps (2 m x 4 n), warp tile 64x32.
// BK=32, double-buffered cp.async smem, 80B row stride (16B pad, conflict-free
// ldmatrix). m16n8k16 fragments via ldmatrix.x4.
// ---------------------------------------------------------------------------
#define RSB 80                       // smem row stride bytes (32 bf16 + 8 pad)
#define GMAT (128 * RSB)             // 10240 B, one matrix tile
#define GSTAGE (4 * GMAT)            // Ah|Al|Bh|Bl = 40960 B
#define GSMEM (2 * GSTAGE)           // 81920 B

__global__ __launch_bounds__(256) void tc_gemm(
    const __nv_bfloat16* __restrict__ Ah, const __nv_bfloat16* __restrict__ Al,
    const __nv_bfloat16* __restrict__ Bh, const __nv_bfloat16* __restrict__ Bl,
    float* __restrict__ C, int M, int N, int K)
{
    extern __shared__ __align__(16) char dsm[];
    const uint32_t base = smem_u32(dsm);

    const int tid  = threadIdx.x;
    const int wid  = tid >> 5;
    const int lane = tid & 31;
    const int wm   = wid >> 2;            // warp m index (0..1) -> 64 rows
    const int wn   = wid & 3;             // warp n index (0..3) -> 32 cols
    const int bm   = blockIdx.y * 128, bn = blockIdx.x * 128;

    // ldmatrix lane geometry (x4): lanes 0-7 m0-7/k0-7, 8-15 m8-15/k0-7,
    // 16-23 m0-7/k8-15, 24-31 m8-15/k8-15
    const int lrow = (lane & 7) + ((lane >> 3) & 1) * 8;
    const int lkof = (lane >> 4) * 8;

    float acc[4][4][4];                   // [mt][nt][c0..c3]
    #pragma unroll
    for (int mt = 0; mt < 4; mt++)
        #pragma unroll
        for (int nt = 0; nt < 4; nt++)
            #pragma unroll
            for (int c = 0; c < 4; c++) acc[mt][nt][c] = 0.f;

    const int lr = tid >> 2;              // load row 0..63
    const int lc = tid & 3;               // load col group 0..3 (16B units)

    // stage loader: 4 matrices x 128 rows x 64B; explicit, no pointer arrays
    auto stage_load = [&](int s, int k0) {
        uint32_t b = base + s * GSTAGE;
        uint32_t so = (uint32_t)(lr * RSB + lc * 16);
        size_t   ga = (size_t)(bm + lr) * K + k0 + lc * 8;
        size_t   gb = (size_t)(bn + lr) * K + k0 + lc * 8;
        cp16(b + so,                          Ah + ga);
        cp16(b + so + 64 * RSB,               Ah + ga + (size_t)64 * K);
        cp16(b + GMAT + so,                   Al + ga);
        cp16(b + GMAT + so + 64 * RSB,        Al + ga + (size_t)64 * K);
        cp16(b + 2 * GMAT + so,               Bh + gb);
        cp16(b + 2 * GMAT + so + 64 * RSB,    Bh + gb + (size_t)64 * K);
        cp16(b + 3 * GMAT + so,               Bl + gb);
        cp16(b + 3 * GMAT + so + 64 * RSB,    Bl + gb + (size_t)64 * K);
        cp_commit();
    };

    const int NCH = K / 32;
    stage_load(0, 0);

    for (int t = 0; t < NCH; t++) {
        if (t + 1 < NCH) {
            stage_load((t + 1) & 1, (t + 1) * 32);
            cp_wait<1>();
        } else {
            cp_wait<0>();
        }
        __syncthreads();

        uint32_t sb = base + (t & 1) * GSTAGE;
        uint32_t aH = sb,            aL = sb + GMAT;
        uint32_t bH = sb + 2 * GMAT, bL = sb + 3 * GMAT;

        #pragma unroll
        for (int ks = 0; ks < 2; ks++) {
            const uint32_t kbyte = (uint32_t)(ks * 16 + lkof) * 2;

            // B fragments: 2 x4 loads per matrix cover 4 n-tiles
            uint32_t bh[4][2], bl[4][2];
            #pragma unroll
            for (int p = 0; p < 2; p++) {
                uint32_t roff = (uint32_t)(wn * 32 + p * 16 + lrow) * RSB + kbyte;
                uint32_t r0, r1, r2, r3;
                ldsm_x4(r0, r1, r2, r3, bH + roff);
                bh[p * 2][0] = r0; bh[p * 2][1] = r2;
                bh[p * 2 + 1][0] = r1; bh[p * 2 + 1][1] = r3;
                ldsm_x4(r0, r1, r2, r3, bL + roff);
                bl[p * 2][0] = r0; bl[p * 2][1] = r2;
                bl[p * 2 + 1][0] = r1; bl[p * 2 + 1][1] = r3;
            }

            #pragma unroll
            for (int mt = 0; mt < 4; mt++) {
                uint32_t roff = (uint32_t)(wm * 64 + mt * 16 + lrow) * RSB + kbyte;
                uint32_t ah0, ah1, ah2, ah3, al0, al1, al2, al3;
                ldsm_x4(ah0, ah1, ah2, ah3, aH + roff);
                ldsm_x4(al0, al1, al2, al3, aL + roff);
                #pragma unroll
                for (int nt = 0; nt < 4; nt++) {
                    float* c = acc[mt][nt];
                    mma16816(c[0], c[1], c[2], c[3], ah0, ah1, ah2, ah3,
                             bh[nt][0], bh[nt][1]);
                    mma16816(c[0], c[1], c[2], c[3], ah0, ah1, ah2, ah3,
                             bl[nt][0], bl[nt][1]);
                    mma16816(c[0], c[1], c[2], c[3], al0, al1, al2, al3,
                             bh[nt][0], bh[nt][1]);
                }
            }
        }
        __syncthreads();
    }

    // epilogue: c0,c1 -> (row g, col 2t..2t+1); c2,c3 -> row g+8
    const int g  = lane >> 2;
    const int tg = lane & 3;
    #pragma unroll
    for (int mt = 0; mt < 4; mt++) {
        #pragma unroll
        for (int nt = 0; nt < 4; nt++) {
            int row = bm + wm * 64 + mt * 16 + g;
            int col = bn + wn * 32 + nt * 8 + tg * 2;
            float* c = acc[mt][nt];
            *(float2*)(C + (size_t)row * N + col)       = make_float2(c[0], c[1]);
            *(float2*)(C + (size_t)(row + 8) * N + col) = make_float2(c[2], c[3]);
        }
    }
}

// ---------------------------------------------------------------------------
// Causal flash attention, fp32, GEMM-tiled (unchanged from round 4 — passing).
// ---------------------------------------------------------------------------
__global__ __launch_bounds__(256) void attn_kernel(
    const float* __restrict__ qkv, float* __restrict__ out)
{
    extern __shared__ float sm[];
    float* Qs   = sm;                    // [64][128] d-major (transposed)
    float* Ks   = Qs + 64 * 128;         // [64][64]  d-major (transposed)
    float* Vs   = Ks + 64 * 64;          // [64][64]  key-major
    float* Pt   = Vs + 64 * 64;          // [64][128] key-major (P transposed)
    float* mrow = Pt + 64 * 128;         // [128]
    float* lrow = mrow + 128;            // [128]
    float* pmax = lrow + 128;            // [128][9]
    float* psum = pmax + 128 * 9;        // [128][9]

    const int h   = blockIdx.y;
    const int bx  = (gridDim.x - 1) - blockIdx.x;   // heavy blocks first
    const int q0  = bx * 128;
    const int tid = threadIdx.x;
    const int cg  = tid >> 5;
    const int rg  = tid & 31;
    const int r0  = rg * 4;
    const int c0  = cg * 8;

    const float sc = 0.125f * 1.4426950408889634f;

    #pragma unroll
    for (int it = 0; it < 8; it++) {
        int idx = it * 256 + tid;
        int row = idx >> 4;
        int f4  = (idx & 15) * 4;
        const float* qp = qkv + (size_t)(q0 + row) * (3 * DD) + h * HDIM + f4;
        float4 v = *(const float4*)qp;
        Qs[(f4 + 0) * 128 + row] = v.x * sc;
        Qs[(f4 + 1) * 128 + row] = v.y * sc;
        Qs[(f4 + 2) * 128 + row] = v.z * sc;
        Qs[(f4 + 3) * 128 + row] = v.w * sc;
    }
    if (tid < 128) { mrow[tid] = -INFINITY; lrow[tid] = 0.f; }

    float accO[4][8];
    #pragma unroll
    for (int i = 0; i < 4; i++)
        #pragma unroll
        for (int j = 0; j < 8; j++) accO[i][j] = 0.f;

    const int ntiles = (q0 + 128) >> 6;
    for (int t = 0; t < ntiles; t++) {
        const int k0 = t << 6;
        __syncthreads();

        {
            int key = tid >> 2;
            const float* kp = qkv + (size_t)(k0 + key) * (3 * DD) + DD + h * HDIM;
            #pragma unroll
            for (int it = 0; it < 4; it++) {
                int f4 = ((tid & 3) + it * 4) * 4;
                float4 v = *(const float4*)(kp + f4);
                Ks[(f4 + 0) * 64 + key] = v.x;
                Ks[(f4 + 1) * 64 + key] = v.y;
                Ks[(f4 + 2) * 64 + key] = v.z;
                Ks[(f4 + 3) * 64 + key] = v.w;
            }
        }
        #pragma unroll
        for (int it = 0; it < 4; it++) {
            int idx = it * 256 + tid;
            int key = idx >> 4;
            int f4  = (idx & 15) * 4;
            const float* vp = qkv + (size_t)(k0 + key) * (3 * DD) + 2 * DD + h * HDIM + f4;
            *(float4*)&Vs[key * 64 + f4] = *(const float4*)vp;
        }
        __syncthreads();

        float s[4][8];
        #pragma unroll
        for (int i = 0; i < 4; i++)
            #pragma unroll
            for (int j = 0; j < 8; j++) s[i][j] = 0.f;

        #pragma unroll 16
        for (int d = 0; d < 64; d++) {
            float4 qa = *(const float4*)&Qs[d * 128 + r0];
            float4 b0 = *(const float4*)&Ks[d * 64 + c0];
            float4 b1 = *(const float4*)&Ks[d * 64 + c0 + 4];
            float aa[4] = {qa.x, qa.y, qa.z, qa.w};
            float bb[8] = {b0.x, b0.y, b0.z, b0.w, b1.x, b1.y, b1.z, b1.w};
            #pragma unroll
            for (int i = 0; i < 4; i++)
                #pragma unroll
                for (int j = 0; j < 8; j++)
                    s[i][j] = fmaf(aa[i], bb[j], s[i][j]);
        }

        if (k0 + 64 > q0) {
            #pragma unroll
            for (int i = 0; i < 4; i++)
                #pragma unroll
                for (int j = 0; j < 8; j++)
                    if (k0 + c0 + j > q0 + r0 + i) s[i][j] = -INFINITY;
        }

        #pragma unroll
        for (int i = 0; i < 4; i++) {
            float pm = s[i][0];
            #pragma unroll
            for (int j = 1; j < 8; j++) pm = fmaxf(pm, s[i][j]);
            pmax[(r0 + i) * 9 + cg] = pm;
        }
        __syncthreads();

        float cf[4];
        #pragma unroll
        for (int i = 0; i < 4; i++) {
            int row = r0 + i;
            float mold = mrow[row];
            float mx = mold;
            #pragma unroll
            for (int g = 0; g < 8; g++) mx = fmaxf(mx, pmax[row * 9 + g]);
            cf[i] = fast_exp2(mold - mx);
            float ps = 0.f;
            #pragma unroll
            for (int j = 0; j < 8; j++) {
                float p = fast_exp2(s[i][j] - mx);
                ps += p;
                Pt[(c0 + j) * 128 + row] = p;
            }
            psum[row * 9 + cg] = ps;
        }
        __syncthreads();

        if (tid < 128) {
            int row = tid;
            float mold = mrow[row];
            float mx = mold;
            #pragma unroll
            for (int g = 0; g < 8; g++) mx = fmaxf(mx, pmax[row * 9 + g]);
            float c = fast_exp2(mold - mx);
            float sum = 0.f;
            #pragma unroll
            for (int g = 0; g < 8; g++) sum += psum[row * 9 + g];
            lrow[row] = lrow[row] * c + sum;
            mrow[row] = mx;
        }
        __syncthreads();

        #pragma unroll
        for (int i = 0; i < 4; i++) {
            float c = cf[i];
            #pragma unroll
            for (int j = 0; j < 8; j++) accO[i][j] *= c;
        }
        #pragma unroll 16
        for (int k = 0; k < 64; k++) {
            float4 pa = *(const float4*)&Pt[k * 128 + r0];
            float4 v0 = *(const float4*)&Vs[k * 64 + c0];
            float4 v1 = *(const float4*)&Vs[k * 64 + c0 + 4];
            float aa[4] = {pa.x, pa.y, pa.z, pa.w};
            float bb[8] = {v0.x, v0.y, v0.z, v0.w, v1.x, v1.y, v1.z, v1.w};
            #pragma unroll
            for (int i = 0; i < 4; i++)
                #pragma unroll
                for (int j = 0; j < 8; j++)
                    accO[i][j] = fmaf(aa[i], bb[j], accO[i][j]);
        }
    }

    #pragma unroll
    for (int i = 0; i < 4; i++) {
        int row = q0 + r0 + i;
        float inv = 1.0f / lrow[r0 + i];
        float4 o0, o1;
        o0.x = accO[i][0] * inv; o0.y = accO[i][1] * inv;
        o0.z = accO[i][2] * inv; o0.w = accO[i][3] * inv;
        o1.x = accO[i][4] * inv; o1.y = accO[i][5] * inv;
        o1.z = accO[i][6] * inv; o1.w = accO[i][7] * inv;
        float* op = out + (size_t)row * DD + h * HDIM + c0;
        *(float4*)op       = o0;
        *(float4*)(op + 4) = o1;
    }
}

static const int ATTN_SMEM = (64 * 128 + 64 * 64 + 64 * 64 + 64 * 128 + 128 + 128 + 128 * 9 + 128 * 9) * 4;

// ---------------------------------------------------------------------------
extern "C" void kernel_launch(void* const* d_in, const int* in_sizes, int n_in,
                              void* d_out, int out_size)
{
    const float* x    = (const float*)d_in[0];
    const float* wqkv = (const float*)d_in[1];
    const float* wout = (const float*)d_in[2];
    float* out = (float*)d_out;

    float *qkv, *att;
    __nv_bfloat16 *xhi, *xlo, *w1hi, *w1lo, *w2hi, *w2lo, *ahi, *alo;
    cudaGetSymbolAddress((void**)&qkv,  g_qkv);
    cudaGetSymbolAddress((void**)&att,  g_att);
    cudaGetSymbolAddress((void**)&xhi,  g_xhi);
    cudaGetSymbolAddress((void**)&xlo,  g_xlo);
    cudaGetSymbolAddress((void**)&w1hi, g_w1hi);
    cudaGetSymbolAddress((void**)&w1lo, g_w1lo);
    cudaGetSymbolAddress((void**)&w2hi, g_w2hi);
    cudaGetSymbolAddress((void**)&w2lo, g_w2lo);
    cudaGetSymbolAddress((void**)&ahi,  g_ahi);
    cudaGetSymbolAddress((void**)&alo,  g_alo);

    cudaFuncSetAttribute(attn_kernel, cudaFuncAttributeMaxDynamicSharedMemorySize, ATTN_SMEM);
    cudaFuncSetAttribute(tc_gemm,     cudaFuncAttributeMaxDynamicSharedMemorySize, GSMEM);

    // prep: split x, transpose+split weights
    split_convert<<<(TT * DD / 4 + 255) / 256, 256>>>(x, xhi, xlo, TT * DD);
    transpose_convert<<<dim3(3 * DD / 32, DD / 32), dim3(32, 8)>>>(wqkv, w1hi, w1lo, DD, 3 * DD);
    transpose_convert<<<dim3(DD / 32, DD / 32), dim3(32, 8)>>>(wout, w2hi, w2lo, DD, DD);

    // 1) QKV projection on tensor cores (mma.sync): (4096x1024) @ (1024x3072)
    tc_gemm<<<dim3(3 * DD / 128, TT / 128), 256, GSMEM>>>(xhi, xlo, w1hi, w1lo, qkv, TT, 3 * DD, DD);

    // 2) causal attention (fp32, unchanged)
    attn_kernel<<<dim3(TT / 128, NH), 256, ATTN_SMEM>>>(qkv, att);

    // split attention output for GEMM2
    split_convert<<<(TT * DD / 4 + 255) / 256, 256>>>(att, ahi, alo, TT * DD);

    // 3) output projection on tensor cores: (4096x1024) @ (1024x1024)
    tc_gemm<<<dim3(DD / 128, TT / 128), 256, GSMEM>>>(ahi, alo, w2hi, w2lo, out, TT, DD, DD);
}

// round 9
// speedup vs baseline: 6.6584x; 1.8797x over previous
#include <cuda_runtime.h>
#include <cuda_bf16.h>
#include <math.h>
#include <stdint.h>

#define TT 4096
#define DD 1024
#define NH 16
#define HDIM 64

// ---------------------------------------------------------------------------
// Scratch (allocation-free rule: device globals). 16B-aligned.
// ---------------------------------------------------------------------------
__device__ __align__(16) float g_qkv[(size_t)TT * 3 * DD];   // 48 MB
__device__ __align__(16) float g_att[(size_t)TT * DD];       // 16 MB
__device__ __align__(16) __nv_bfloat16 g_xhi[(size_t)TT * DD],      g_xlo[(size_t)TT * DD];
__device__ __align__(16) __nv_bfloat16 g_w1hi[(size_t)3 * DD * DD], g_w1lo[(size_t)3 * DD * DD];
__device__ __align__(16) __nv_bfloat16 g_w2hi[(size_t)DD * DD],     g_w2lo[(size_t)DD * DD];
__device__ __align__(16) __nv_bfloat16 g_ahi[(size_t)TT * DD],      g_alo[(size_t)TT * DD];
// attention operands, head-major
__device__ __align__(16) __nv_bfloat16 g_qh[(size_t)NH * TT * HDIM], g_ql[(size_t)NH * TT * HDIM];
__device__ __align__(16) __nv_bfloat16 g_kh[(size_t)NH * TT * HDIM], g_kl[(size_t)NH * TT * HDIM];
__device__ __align__(16) __nv_bfloat16 g_vth[(size_t)NH * HDIM * TT], g_vtl[(size_t)NH * HDIM * TT]; // [h][d][t]

// ---------------------------------------------------------------------------
// PTX helpers
// ---------------------------------------------------------------------------
__device__ __forceinline__ uint32_t smem_u32(const void* p) {
    uint32_t a;
    asm("{ .reg .u64 t; cvta.to.shared.u64 t, %1; cvt.u32.u64 %0, t; }" : "=r"(a) : "l"(p));
    return a;
}
__device__ __forceinline__ void ldsm_x4(uint32_t& r0, uint32_t& r1, uint32_t& r2, uint32_t& r3,
                                        uint32_t addr) {
    asm volatile("ldmatrix.sync.aligned.m8n8.x4.shared.b16 {%0,%1,%2,%3}, [%4];"
                 : "=r"(r0), "=r"(r1), "=r"(r2), "=r"(r3) : "r"(addr));
}
__device__ __forceinline__ void mma16816(float& c0, float& c1, float& c2, float& c3,
                                         uint32_t a0, uint32_t a1, uint32_t a2, uint32_t a3,
                                         uint32_t b0, uint32_t b1) {
    asm volatile("mma.sync.aligned.m16n8k16.row.col.f32.bf16.bf16.f32 "
                 "{%0,%1,%2,%3}, {%4,%5,%6,%7}, {%8,%9}, {%0,%1,%2,%3};"
                 : "+f"(c0), "+f"(c1), "+f"(c2), "+f"(c3)
                 : "r"(a0), "r"(a1), "r"(a2), "r"(a3), "r"(b0), "r"(b1));
}
__device__ __forceinline__ void cp16(uint32_t dst, const void* src) {
    asm volatile("cp.async.cg.shared.global [%0], [%1], 16;" :: "r"(dst), "l"(src) : "memory");
}
__device__ __forceinline__ void cp_commit() { asm volatile("cp.async.commit_group;" ::: "memory"); }
template <int N> __device__ __forceinline__ void cp_wait() {
    asm volatile("cp.async.wait_group %0;" :: "n"(N) : "memory");
}
__device__ __forceinline__ float fast_exp2(float x) {
    float y;
    asm("ex2.approx.ftz.f32 %0, %1;" : "=f"(y) : "f"(x));
    return y;
}
__device__ __forceinline__ uint32_t pack_bf16x2(float a, float b) {
    __nv_bfloat162 t = __floats2bfloat162_rn(a, b);
    return *reinterpret_cast<uint32_t*>(&t);
}

// ---------------------------------------------------------------------------
// fp32 -> (hi, lo) bf16 split, elementwise.
// ---------------------------------------------------------------------------
__global__ void split_convert(const float* __restrict__ s,
                              __nv_bfloat16* __restrict__ hi,
                              __nv_bfloat16* __restrict__ lo, int n)
{
    int i = (blockIdx.x * blockDim.x + threadIdx.x) * 4;
    if (i >= n) return;
    float4 v = *(const float4*)(s + i);
    float h0 = __bfloat162float(__float2bfloat16(v.x));
    float h1 = __bfloat162float(__float2bfloat16(v.y));
    float h2 = __bfloat162float(__float2bfloat16(v.z));
    float h3 = __bfloat162float(__float2bfloat16(v.w));
    uint2 hh, ll;
    hh.x = pack_bf16x2(h0, h1);
    hh.y = pack_bf16x2(h2, h3);
    ll.x = pack_bf16x2(v.x - h0, v.y - h1);
    ll.y = pack_bf16x2(v.z - h2, v.w - h3);
    *(uint2*)(hi + i) = hh;
    *(uint2*)(lo + i) = ll;
}

// ---------------------------------------------------------------------------
// w[K][N] fp32 -> wT hi/lo [N][K] bf16.
// ---------------------------------------------------------------------------
__global__ void transpose_convert(const float* __restrict__ w,
                                  __nv_bfloat16* __restrict__ hi,
                                  __nv_bfloat16* __restrict__ lo, int K, int N)
{
    __shared__ float t[32][33];
    int n0 = blockIdx.x * 32, k0 = blockIdx.y * 32;
    int tx = threadIdx.x, ty = threadIdx.y;
    for (int j = ty; j < 32; j += 8)
        t[j][tx] = w[(size_t)(k0 + j) * N + n0 + tx];
    __syncthreads();
    for (int j = ty; j < 32; j += 8) {
        float v = t[tx][j];
        __nv_bfloat16 h = __float2bfloat16(v);
        __nv_bfloat16 l = __float2bfloat16(v - __bfloat162float(h));
        size_t o = (size_t)(n0 + j) * K + k0 + tx;
        hi[o] = h; lo[o] = l;
    }
}

// ---------------------------------------------------------------------------
// qkv fp32 -> Q (scaled) and K head-major hi/lo splits: [h][t][64]
// ---------------------------------------------------------------------------
__global__ void qk_split(const float* __restrict__ qkv,
                         __nv_bfloat16* __restrict__ qh, __nv_bfloat16* __restrict__ ql,
                         __nv_bfloat16* __restrict__ kh, __nv_bfloat16* __restrict__ kl)
{
    const float sc = 0.125f * 1.4426950408889634f;
    size_t i4 = ((size_t)blockIdx.x * blockDim.x + threadIdx.x) * 4;  // over NH*TT*64
    int d = (int)(i4 & 63);
    int t = (int)((i4 >> 6) & (TT - 1));
    int h = (int)(i4 >> 18);
    const float* qp = qkv + (size_t)t * (3 * DD) + h * HDIM + d;
    float4 q = *(const float4*)qp;
    float4 k = *(const float4*)(qp + DD);
    q.x *= sc; q.y *= sc; q.z *= sc; q.w *= sc;
    float qh0 = __bfloat162float(__float2bfloat16(q.x));
    float qh1 = __bfloat162float(__float2bfloat16(q.y));
    float qh2 = __bfloat162float(__float2bfloat16(q.z));
    float qh3 = __bfloat162float(__float2bfloat16(q.w));
    float kh0 = __bfloat162float(__float2bfloat16(k.x));
    float kh1 = __bfloat162float(__float2bfloat16(k.y));
    float kh2 = __bfloat162float(__float2bfloat16(k.z));
    float kh3 = __bfloat162float(__float2bfloat16(k.w));
    uint2 v;
    v.x = pack_bf16x2(qh0, qh1); v.y = pack_bf16x2(qh2, qh3);
    *(uint2*)(qh + i4) = v;
    v.x = pack_bf16x2(q.x - qh0, q.y - qh1); v.y = pack_bf16x2(q.z - qh2, q.w - qh3);
    *(uint2*)(ql + i4) = v;
    v.x = pack_bf16x2(kh0, kh1); v.y = pack_bf16x2(kh2, kh3);
    *(uint2*)(kh + i4) = v;
    v.x = pack_bf16x2(k.x - kh0, k.y - kh1); v.y = pack_bf16x2(k.z - kh2, k.w - kh3);
    *(uint2*)(kl + i4) = v;
}

// ---------------------------------------------------------------------------
// qkv V part -> transposed hi/lo: vt[h][d][t]
// ---------------------------------------------------------------------------
__global__ void vt_split(const float* __restrict__ qkv,
                         __nv_bfloat16* __restrict__ vth, __nv_bfloat16* __restrict__ vtl)
{
    __shared__ float sm[32][33];
    int t0 = blockIdx.x * 32, d0 = blockIdx.y * 32, h = blockIdx.z;
    int tx = threadIdx.x, ty = threadIdx.y;
    for (int j = ty; j < 32; j += 8)
        sm[j][tx] = qkv[(size_t)(t0 + j) * (3 * DD) + 2 * DD + h * HDIM + d0 + tx];
    __syncthreads();
    for (int j = ty; j < 32; j += 8) {
        float v = sm[tx][j];            // element (t0+tx, d0+j)
        __nv_bfloat16 hh = __float2bfloat16(v);
        __nv_bfloat16 ll = __float2bfloat16(v - __bfloat162float(hh));
        size_t o = ((size_t)h * HDIM + d0 + j) * TT + t0 + tx;
        vth[o] = hh; vtl[o] = ll;
    }
}

// ---------------------------------------------------------------------------
// mma.sync bf16 split GEMM (unchanged from round 8 — passing)
// ---------------------------------------------------------------------------
#define RSB 80
#define GMAT (128 * RSB)
#define GSTAGE (4 * GMAT)
#define GSMEM (2 * GSTAGE)

__global__ __launch_bounds__(256) void tc_gemm(
    const __nv_bfloat16* __restrict__ Ah, const __nv_bfloat16* __restrict__ Al,
    const __nv_bfloat16* __restrict__ Bh, const __nv_bfloat16* __restrict__ Bl,
    float* __restrict__ C, int M, int N, int K)
{
    extern __shared__ __align__(16) char dsm[];
    const uint32_t base = smem_u32(dsm);

    const int tid  = threadIdx.x;
    const int wid  = tid >> 5;
    const int lane = tid & 31;
    const int wm   = wid >> 2;
    const int wn   = wid & 3;
    const int bm   = blockIdx.y * 128, bn = blockIdx.x * 128;

    const int lrow = (lane & 7) + ((lane >> 3) & 1) * 8;
    const int lkof = (lane >> 4) * 8;

    float acc[4][4][4];
    #pragma unroll
    for (int mt = 0; mt < 4; mt++)
        #pragma unroll
        for (int nt = 0; nt < 4; nt++)
            #pragma unroll
            for (int c = 0; c < 4; c++) acc[mt][nt][c] = 0.f;

    const int lr = tid >> 2;
    const int lc = tid & 3;

    auto stage_load = [&](int s, int k0) {
        uint32_t b = base + s * GSTAGE;
        uint32_t so = (uint32_t)(lr * RSB + lc * 16);
        size_t   ga = (size_t)(bm + lr) * K + k0 + lc * 8;
        size_t   gb = (size_t)(bn + lr) * K + k0 + lc * 8;
        cp16(b + so,                          Ah + ga);
        cp16(b + so + 64 * RSB,               Ah + ga + (size_t)64 * K);
        cp16(b + GMAT + so,                   Al + ga);
        cp16(b + GMAT + so + 64 * RSB,        Al + ga + (size_t)64 * K);
        cp16(b + 2 * GMAT + so,               Bh + gb);
        cp16(b + 2 * GMAT + so + 64 * RSB,    Bh + gb + (size_t)64 * K);
        cp16(b + 3 * GMAT + so,               Bl + gb);
        cp16(b + 3 * GMAT + so + 64 * RSB,    Bl + gb + (size_t)64 * K);
        cp_commit();
    };

    const int NCH = K / 32;
    stage_load(0, 0);

    for (int t = 0; t < NCH; t++) {
        if (t + 1 < NCH) {
            stage_load((t + 1) & 1, (t + 1) * 32);
            cp_wait<1>();
        } else {
            cp_wait<0>();
        }
        __syncthreads();

        uint32_t sb = base + (t & 1) * GSTAGE;
        uint32_t aH = sb,            aL = sb + GMAT;
        uint32_t bH = sb + 2 * GMAT, bL = sb + 3 * GMAT;

        #pragma unroll
        for (int ks = 0; ks < 2; ks++) {
            const uint32_t kbyte = (uint32_t)(ks * 16 + lkof) * 2;

            uint32_t bh[4][2], bl[4][2];
            #pragma unroll
            for (int p = 0; p < 2; p++) {
                uint32_t roff = (uint32_t)(wn * 32 + p * 16 + lrow) * RSB + kbyte;
                uint32_t r0, r1, r2, r3;
                ldsm_x4(r0, r1, r2, r3, bH + roff);
                bh[p * 2][0] = r0; bh[p * 2][1] = r2;
                bh[p * 2 + 1][0] = r1; bh[p * 2 + 1][1] = r3;
                ldsm_x4(r0, r1, r2, r3, bL + roff);
                bl[p * 2][0] = r0; bl[p * 2][1] = r2;
                bl[p * 2 + 1][0] = r1; bl[p * 2 + 1][1] = r3;
            }

            #pragma unroll
            for (int mt = 0; mt < 4; mt++) {
                uint32_t roff = (uint32_t)(wm * 64 + mt * 16 + lrow) * RSB + kbyte;
                uint32_t ah0, ah1, ah2, ah3, al0, al1, al2, al3;
                ldsm_x4(ah0, ah1, ah2, ah3, aH + roff);
                ldsm_x4(al0, al1, al2, al3, aL + roff);
                #pragma unroll
                for (int nt = 0; nt < 4; nt++) {
                    float* c = acc[mt][nt];
                    mma16816(c[0], c[1], c[2], c[3], ah0, ah1, ah2, ah3,
                             bh[nt][0], bh[nt][1]);
                    mma16816(c[0], c[1], c[2], c[3], ah0, ah1, ah2, ah3,
                             bl[nt][0], bl[nt][1]);
                    mma16816(c[0], c[1], c[2], c[3], al0, al1, al2, al3,
                             bh[nt][0], bh[nt][1]);
                }
            }
        }
        __syncthreads();
    }

    const int g  = lane >> 2;
    const int tg = lane & 3;
    #pragma unroll
    for (int mt = 0; mt < 4; mt++) {
        #pragma unroll
        for (int nt = 0; nt < 4; nt++) {
            int row = bm + wm * 64 + mt * 16 + g;
            int col = bn + wn * 32 + nt * 8 + tg * 2;
            float* c = acc[mt][nt];
            *(float2*)(C + (size_t)row * N + col)       = make_float2(c[0], c[1]);
            *(float2*)(C + (size_t)(row + 8) * N + col) = make_float2(c[2], c[3]);
        }
    }
}

// ---------------------------------------------------------------------------
// Flash attention on mma.sync bf16 (split). Block = 128 queries x 1 head,
// 8 warps x 16 rows. Q fragments register-resident; K/V tiles (64 keys)
// double-buffered via cp.async. Online softmax in registers; l as per-lane
// partial reduced once at the end.
// smem rows: 64 bf16 = 128B + 16B pad = 144B stride (conflict-free ldmatrix).
// ---------------------------------------------------------------------------
#define RSB2 144
#define KMAT (64 * RSB2)       // 9216
#define KSTG (4 * KMAT)        // Kh|Kl|Vh|Vl = 36864
#define ASMEM (2 * KSTG)       // 73728

__global__ __launch_bounds__(256, 1) void attn_mma(
    const __nv_bfloat16* __restrict__ Qh, const __nv_bfloat16* __restrict__ Ql,
    const __nv_bfloat16* __restrict__ Kh, const __nv_bfloat16* __restrict__ Kl,
    const __nv_bfloat16* __restrict__ Vth, const __nv_bfloat16* __restrict__ Vtl,
    float* __restrict__ out)
{
    extern __shared__ __align__(16) char asmem[];
    const uint32_t base = smem_u32(asmem);

    const int h   = blockIdx.y;
    const int bx  = (gridDim.x - 1) - blockIdx.x;   // heavy blocks first
    const int q0  = bx * 128;
    const int tid = threadIdx.x;
    const int w   = tid >> 5;
    const int lane = tid & 31;
    const int g   = lane >> 2;
    const int cq  = lane & 3;
    const int lrow = (lane & 7) + ((lane >> 3) & 1) * 8;
    const int lkof = (lane >> 4) * 8;

    // ---- stage Q tile into smem (hi at 0, lo at 128*RSB2), ldmatrix to regs
    {
        #pragma unroll
        for (int it = 0; it < 4; it++) {
            int slot = tid + it * 256;           // 0..1023
            int row = slot >> 3, gg = slot & 7;
            size_t qo = ((size_t)h * TT + q0 + row) * HDIM + gg * 8;
            cp16(base + row * RSB2 + gg * 16,              Qh + qo);
            cp16(base + 128 * RSB2 + row * RSB2 + gg * 16, Ql + qo);
        }
        cp_commit();
        cp_wait<0>();
    }
    __syncthreads();
    uint32_t qh[4][4], ql[4][4];
    #pragma unroll
    for (int ks = 0; ks < 4; ks++) {
        uint32_t addr = base + (uint32_t)(w * 16 + lrow) * RSB2 + (uint32_t)(ks * 16 + lkof) * 2;
        ldsm_x4(qh[ks][0], qh[ks][1], qh[ks][2], qh[ks][3], addr);
        ldsm_x4(ql[ks][0], ql[ks][1], ql[ks][2], ql[ks][3], addr + 128 * RSB2);
    }
    __syncthreads();   // Q consumed; stage buffers free

    float o[8][4];
    #pragma unroll
    for (int dt = 0; dt < 8; dt++)
        #pragma unroll
        for (int c = 0; c < 4; c++) o[dt][c] = 0.f;
    float m0 = -INFINITY, m1 = -INFINITY, lp0 = 0.f, lp1 = 0.f;

    auto stage_kv = [&](int s, int k0) {
        uint32_t b = base + s * KSTG;
        #pragma unroll
        for (int it = 0; it < 2; it++) {
            int slot = tid + it * 256;           // 0..511
            int row = slot >> 3, gg = slot & 7;
            uint32_t so = (uint32_t)(row * RSB2 + gg * 16);
            size_t ko = ((size_t)h * TT + k0 + row) * HDIM + gg * 8;
            size_t vo = ((size_t)h * HDIM + row) * TT + k0 + gg * 8;
            cp16(b + so,            Kh + ko);
            cp16(b + KMAT + so,     Kl + ko);
            cp16(b + 2 * KMAT + so, Vth + vo);
            cp16(b + 3 * KMAT + so, Vtl + vo);
        }
        cp_commit();
    };

    const int ntiles = (q0 + 128) >> 6;
    stage_kv(0, 0);

    const int row0 = q0 + w * 16 + g;

    for (int t = 0; t < ntiles; t++) {
        const int k0 = t << 6;
        if (t + 1 < ntiles) {
            stage_kv((t + 1) & 1, (t + 1) * 64);
            cp_wait<1>();
        } else {
            cp_wait<0>();
        }
        __syncthreads();

        uint32_t sb = base + (t & 1) * KSTG;

        // ---- S = Q K^T (3-term split), 8 key-ntiles of n=8
        float s[8][4];
        #pragma unroll
        for (int nt = 0; nt < 8; nt++)
            #pragma unroll
            for (int c = 0; c < 4; c++) s[nt][c] = 0.f;

        #pragma unroll
        for (int ks = 0; ks < 4; ks++) {
            const uint32_t kb = (uint32_t)(ks * 16 + lkof) * 2;
            #pragma unroll
            for (int p = 0; p < 4; p++) {
                uint32_t roff = (uint32_t)(p * 16 + lrow) * RSB2 + kb;
                uint32_t r0, r1, r2, r3, u0, u1, u2, u3;
                ldsm_x4(r0, r1, r2, r3, sb + roff);          // Kh
                ldsm_x4(u0, u1, u2, u3, sb + KMAT + roff);   // Kl
                float* s0 = s[2 * p];
                float* s1 = s[2 * p + 1];
                mma16816(s0[0], s0[1], s0[2], s0[3], qh[ks][0], qh[ks][1], qh[ks][2], qh[ks][3], r0, r2);
                mma16816(s0[0], s0[1], s0[2], s0[3], qh[ks][0], qh[ks][1], qh[ks][2], qh[ks][3], u0, u2);
                mma16816(s0[0], s0[1], s0[2], s0[3], ql[ks][0], ql[ks][1], ql[ks][2], ql[ks][3], r0, r2);
                mma16816(s1[0], s1[1], s1[2], s1[3], qh[ks][0], qh[ks][1], qh[ks][2], qh[ks][3], r1, r3);
                mma16816(s1[0], s1[1], s1[2], s1[3], qh[ks][0], qh[ks][1], qh[ks][2], qh[ks][3], u1, u3);
                mma16816(s1[0], s1[1], s1[2], s1[3], ql[ks][0], ql[ks][1], ql[ks][2], ql[ks][3], r1, r3);
            }
        }

        // ---- causal mask (only final two tiles can clip)
        if (k0 + 64 > q0) {
            #pragma unroll
            for (int nt = 0; nt < 8; nt++) {
                int col = k0 + nt * 8 + 2 * cq;
                if (col     > row0)     s[nt][0] = -INFINITY;
                if (col + 1 > row0)     s[nt][1] = -INFINITY;
                if (col     > row0 + 8) s[nt][2] = -INFINITY;
                if (col + 1 > row0 + 8) s[nt][3] = -INFINITY;
            }
        }

        // ---- online softmax (log2 domain; Q pre-scaled)
        float mx0 = -INFINITY, mx1 = -INFINITY;
        #pragma unroll
        for (int nt = 0; nt < 8; nt++) {
            mx0 = fmaxf(mx0, fmaxf(s[nt][0], s[nt][1]));
            mx1 = fmaxf(mx1, fmaxf(s[nt][2], s[nt][3]));
        }
        mx0 = fmaxf(mx0, __shfl_xor_sync(0xffffffffu, mx0, 1));
        mx0 = fmaxf(mx0, __shfl_xor_sync(0xffffffffu, mx0, 2));
        mx1 = fmaxf(mx1, __shfl_xor_sync(0xffffffffu, mx1, 1));
        mx1 = fmaxf(mx1, __shfl_xor_sync(0xffffffffu, mx1, 2));
        float mn0 = fmaxf(m0, mx0), mn1 = fmaxf(m1, mx1);
        float cf0 = fast_exp2(m0 - mn0), cf1 = fast_exp2(m1 - mn1);
        m0 = mn0; m1 = mn1;
        lp0 *= cf0; lp1 *= cf1;
        #pragma unroll
        for (int dt = 0; dt < 8; dt++) {
            o[dt][0] *= cf0; o[dt][1] *= cf0;
            o[dt][2] *= cf1; o[dt][3] *= cf1;
        }

        uint32_t pah0[8], pah1[8], pal0[8], pal1[8];
        #pragma unroll
        for (int nt = 0; nt < 8; nt++) {
            float p0 = fast_exp2(s[nt][0] - m0);
            float p1 = fast_exp2(s[nt][1] - m0);
            float p2 = fast_exp2(s[nt][2] - m1);
            float p3 = fast_exp2(s[nt][3] - m1);
            lp0 += p0 + p1; lp1 += p2 + p3;
            float h0 = __bfloat162float(__float2bfloat16(p0));
            float h1 = __bfloat162float(__float2bfloat16(p1));
            float h2 = __bfloat162float(__float2bfloat16(p2));
            float h3 = __bfloat162float(__float2bfloat16(p3));
            pah0[nt] = pack_bf16x2(h0, h1);
            pah1[nt] = pack_bf16x2(h2, h3);
            pal0[nt] = pack_bf16x2(p0 - h0, p1 - h1);
            pal1[nt] = pack_bf16x2(p2 - h2, p3 - h3);
        }

        // ---- O += P V (3-term split). keys are the mma K dim (16/step).
        #pragma unroll
        for (int kk = 0; kk < 4; kk++) {
            uint32_t ah0 = pah0[2 * kk], ah1 = pah1[2 * kk];
            uint32_t ah2 = pah0[2 * kk + 1], ah3 = pah1[2 * kk + 1];
            uint32_t al0 = pal0[2 * kk], al1 = pal1[2 * kk];
            uint32_t al2 = pal0[2 * kk + 1], al3 = pal1[2 * kk + 1];
            const uint32_t kb = (uint32_t)(kk * 16 + lkof) * 2;
            #pragma unroll
            for (int dp = 0; dp < 4; dp++) {
                uint32_t roff = (uint32_t)(dp * 16 + lrow) * RSB2 + kb;
                uint32_t v0, v1, v2, v3, x0, x1, x2, x3;
                ldsm_x4(v0, v1, v2, v3, sb + 2 * KMAT + roff);   // Vh
                ldsm_x4(x0, x1, x2, x3, sb + 3 * KMAT + roff);   // Vl
                float* oa = o[2 * dp];
                float* ob = o[2 * dp + 1];
                mma16816(oa[0], oa[1], oa[2], oa[3], ah0, ah1, ah2, ah3, v0, v2);
                mma16816(oa[0], oa[1], oa[2], oa[3], ah0, ah1, ah2, ah3, x0, x2);
                mma16816(oa[0], oa[1], oa[2], oa[3], al0, al1, al2, al3, v0, v2);
                mma16816(ob[0], ob[1], ob[2], ob[3], ah0, ah1, ah2, ah3, v1, v3);
                mma16816(ob[0], ob[1], ob[2], ob[3], ah0, ah1, ah2, ah3, x1, x3);
                mma16816(ob[0], ob[1], ob[2], ob[3], al0, al1, al2, al3, v1, v3);
            }
        }
        __syncthreads();
    }

    // ---- epilogue: reduce l across the 4 lanes of each row, write
    lp0 += __shfl_xor_sync(0xffffffffu, lp0, 1);
    lp0 += __shfl_xor_sync(0xffffffffu, lp0, 2);
    lp1 += __shfl_xor_sync(0xffffffffu, lp1, 1);
    lp1 += __shfl_xor_sync(0xffffffffu, lp1, 2);
    float inv0 = 1.0f / lp0, inv1 = 1.0f / lp1;
    #pragma unroll
    for (int dt = 0; dt < 8; dt++) {
        int col = h * HDIM + dt * 8 + 2 * cq;
        *(float2*)(out + (size_t)row0 * DD + col) =
            make_float2(o[dt][0] * inv0, o[dt][1] * inv0);
        *(float2*)(out + (size_t)(row0 + 8) * DD + col) =
            make_float2(o[dt][2] * inv1, o[dt][3] * inv1);
    }
}

// ---------------------------------------------------------------------------
extern "C" void kernel_launch(void* const* d_in, const int* in_sizes, int n_in,
                              void* d_out, int out_size)
{
    const float* x    = (const float*)d_in[0];
    const float* wqkv = (const float*)d_in[1];
    const float* wout = (const float*)d_in[2];
    float* out = (float*)d_out;

    float *qkv, *att;
    __nv_bfloat16 *xhi, *xlo, *w1hi, *w1lo, *w2hi, *w2lo, *ahi, *alo;
    __nv_bfloat16 *qh, *ql, *kh, *kl, *vth, *vtl;
    cudaGetSymbolAddress((void**)&qkv,  g_qkv);
    cudaGetSymbolAddress((void**)&att,  g_att);
    cudaGetSymbolAddress((void**)&xhi,  g_xhi);
    cudaGetSymbolAddress((void**)&xlo,  g_xlo);
    cudaGetSymbolAddress((void**)&w1hi, g_w1hi);
    cudaGetSymbolAddress((void**)&w1lo, g_w1lo);
    cudaGetSymbolAddress((void**)&w2hi, g_w2hi);
    cudaGetSymbolAddress((void**)&w2lo, g_w2lo);
    cudaGetSymbolAddress((void**)&ahi,  g_ahi);
    cudaGetSymbolAddress((void**)&alo,  g_alo);
    cudaGetSymbolAddress((void**)&qh,   g_qh);
    cudaGetSymbolAddress((void**)&ql,   g_ql);
    cudaGetSymbolAddress((void**)&kh,   g_kh);
    cudaGetSymbolAddress((void**)&kl,   g_kl);
    cudaGetSymbolAddress((void**)&vth,  g_vth);
    cudaGetSymbolAddress((void**)&vtl,  g_vtl);

    cudaFuncSetAttribute(tc_gemm,  cudaFuncAttributeMaxDynamicSharedMemorySize, GSMEM);
    cudaFuncSetAttribute(attn_mma, cudaFuncAttributeMaxDynamicSharedMemorySize, ASMEM);

    // prep: split x, transpose+split weights
    split_convert<<<(TT * DD / 4 + 255) / 256, 256>>>(x, xhi, xlo, TT * DD);
    transpose_convert<<<dim3(3 * DD / 32, DD / 32), dim3(32, 8)>>>(wqkv, w1hi, w1lo, DD, 3 * DD);
    transpose_convert<<<dim3(DD / 32, DD / 32), dim3(32, 8)>>>(wout, w2hi, w2lo, DD, DD);

    // 1) QKV projection (tensor cores)
    tc_gemm<<<dim3(3 * DD / 128, TT / 128), 256, GSMEM>>>(xhi, xlo, w1hi, w1lo, qkv, TT, 3 * DD, DD);

    // attention operand prep
    qk_split<<<(NH * TT * HDIM / 4 + 255) / 256, 256>>>(qkv, qh, ql, kh, kl);
    vt_split<<<dim3(TT / 32, HDIM / 32, NH), dim3(32, 8)>>>(qkv, vth, vtl);

    // 2) causal attention (tensor cores)
    attn_mma<<<dim3(TT / 128, NH), 256, ASMEM>>>(qh, ql, kh, kl, vth, vtl, att);

    // split attention output for GEMM2
    split_convert<<<(TT * DD / 4 + 255) / 256, 256>>>(att, ahi, alo, TT * DD);

    // 3) output projection (tensor cores)
    tc_gemm<<<dim3(DD / 128, TT / 128), 256, GSMEM>>>(ahi, alo, w2hi, w2lo, out, TT, DD, DD);
}

// round 10
// speedup vs baseline: 7.4214x; 1.1146x over previous
#include <cuda_runtime.h>
#include <cuda_bf16.h>
#include <math.h>
#include <stdint.h>

#define TT 4096
#define DD 1024
#define NH 16
#define HDIM 64

// ---------------------------------------------------------------------------
// Scratch (allocation-free rule: device globals). 16B-aligned.
// GEMM operands are stored chunk-major, hi/lo interleaved, SW128-preswizzled:
//   [kc][row][32 hi bf16 | 32 lo bf16]  (128B per row, kc = K/32 chunks)
// ---------------------------------------------------------------------------
__device__ __align__(16) float g_qkv[(size_t)TT * 3 * DD];   // 48 MB
__device__ __align__(16) float g_att[(size_t)TT * DD];       // 16 MB
__device__ __align__(16) __nv_bfloat16 g_xhl[(size_t)TT * DD * 2];
__device__ __align__(16) __nv_bfloat16 g_w1hl[(size_t)3 * DD * DD * 2];
__device__ __align__(16) __nv_bfloat16 g_w2hl[(size_t)DD * DD * 2];
__device__ __align__(16) __nv_bfloat16 g_ahl[(size_t)TT * DD * 2];
// attention operands, head-major (unchanged from round 9)
__device__ __align__(16) __nv_bfloat16 g_qh[(size_t)NH * TT * HDIM], g_ql[(size_t)NH * TT * HDIM];
__device__ __align__(16) __nv_bfloat16 g_kh[(size_t)NH * TT * HDIM], g_kl[(size_t)NH * TT * HDIM];
__device__ __align__(16) __nv_bfloat16 g_vth[(size_t)NH * HDIM * TT], g_vtl[(size_t)NH * HDIM * TT];

// ---------------------------------------------------------------------------
// PTX helpers
// ---------------------------------------------------------------------------
__device__ __forceinline__ uint32_t smem_u32(const void* p) {
    uint32_t a;
    asm("{ .reg .u64 t; cvta.to.shared.u64 t, %1; cvt.u32.u64 %0, t; }" : "=r"(a) : "l"(p));
    return a;
}
__device__ __forceinline__ void ldsm_x4(uint32_t& r0, uint32_t& r1, uint32_t& r2, uint32_t& r3,
                                        uint32_t addr) {
    asm volatile("ldmatrix.sync.aligned.m8n8.x4.shared.b16 {%0,%1,%2,%3}, [%4];"
                 : "=r"(r0), "=r"(r1), "=r"(r2), "=r"(r3) : "r"(addr));
}
__device__ __forceinline__ void mma16816(float& c0, float& c1, float& c2, float& c3,
                                         uint32_t a0, uint32_t a1, uint32_t a2, uint32_t a3,
                                         uint32_t b0, uint32_t b1) {
    asm volatile("mma.sync.aligned.m16n8k16.row.col.f32.bf16.bf16.f32 "
                 "{%0,%1,%2,%3}, {%4,%5,%6,%7}, {%8,%9}, {%0,%1,%2,%3};"
                 : "+f"(c0), "+f"(c1), "+f"(c2), "+f"(c3)
                 : "r"(a0), "r"(a1), "r"(a2), "r"(a3), "r"(b0), "r"(b1));
}
__device__ __forceinline__ void cp16(uint32_t dst, const void* src) {
    asm volatile("cp.async.cg.shared.global [%0], [%1], 16;" :: "r"(dst), "l"(src) : "memory");
}
__device__ __forceinline__ void cp_commit() { asm volatile("cp.async.commit_group;" ::: "memory"); }
template <int N> __device__ __forceinline__ void cp_wait() {
    asm volatile("cp.async.wait_group %0;" :: "n"(N) : "memory");
}
// bulk async copy global -> shared, completion via mbarrier complete_tx
__device__ __forceinline__ void bulk_g2s(uint32_t dst, const void* src, uint32_t bytes,
                                         uint32_t mbar) {
    asm volatile("cp.async.bulk.shared::cluster.global.mbarrier::complete_tx::bytes "
                 "[%0], [%1], %2, [%3];"
                 :: "r"(dst), "l"(src), "r"(bytes), "r"(mbar) : "memory");
}
#define MBARRIER_INIT(mb, c) \
    asm volatile("mbarrier.init.shared.b64 [%0], %1;" :: "r"((uint32_t)(mb)), "r"((uint32_t)(c)) : "memory")
#define MBARRIER_EXPECT_TX(mb, bytes) \
    asm volatile("mbarrier.arrive.expect_tx.shared.b64 _, [%0], %1;" \
                 :: "r"((uint32_t)(mb)), "r"((uint32_t)(bytes)) : "memory")
#define MBARRIER_WAIT_PARITY(mb, ph) do { \
    uint32_t _m = (uint32_t)(mb), _p = (uint32_t)(ph), _d; \
    asm volatile("{ .reg .pred p; mbarrier.try_wait.parity.acquire.cta.shared::cta.b64 p, [%1], %2; " \
                 "selp.b32 %0, 1, 0, p; }" : "=r"(_d) : "r"(_m), "r"(_p) : "memory"); \
    if (!_d) { \
        asm volatile("{ .reg .pred P1; WL_%=: mbarrier.try_wait.parity.acquire.cta.shared::cta.b64 P1, [%0], %1, 0x989680; " \
                     "@P1 bra.uni WD_%=; bra.uni WL_%=; WD_%=: }" :: "r"(_m), "r"(_p) : "memory"); \
    } \
} while (0)

__device__ __forceinline__ float fast_exp2(float x) {
    float y;
    asm("ex2.approx.ftz.f32 %0, %1;" : "=f"(y) : "f"(x));
    return y;
}
__device__ __forceinline__ uint32_t pack_bf16x2(float a, float b) {
    __nv_bfloat162 t = __floats2bfloat162_rn(a, b);
    return *reinterpret_cast<uint32_t*>(&t);
}
__device__ __forceinline__ uint32_t swz(uint32_t o)  { return o ^ ((o >> 3) & 0x70); }
__device__ __forceinline__ size_t   swzs(size_t o)   { return o ^ ((o >> 3) & 0x70); }

// ---------------------------------------------------------------------------
// fp32 [M][K] -> chunk-major hi/lo interleaved preswizzled bf16 buffer.
// Each thread handles 8 consecutive k of one row (one 16B hi + one 16B lo unit).
// ---------------------------------------------------------------------------
__global__ void split_chunk(const float* __restrict__ s, __nv_bfloat16* __restrict__ o,
                            int M, int K)
{
    size_t i8 = ((size_t)blockIdx.x * blockDim.x + threadIdx.x) * 8;
    if (i8 >= (size_t)M * K) return;
    int m  = (int)(i8 / K);
    int k  = (int)(i8 % K);
    int kc = k >> 5, kin = k & 31;            // kin multiple of 8
    float4 v0 = *(const float4*)(s + i8);
    float4 v1 = *(const float4*)(s + i8 + 4);
    float f[8] = {v0.x, v0.y, v0.z, v0.w, v1.x, v1.y, v1.z, v1.w};
    float h[8];
    #pragma unroll
    for (int j = 0; j < 8; j++) h[j] = __bfloat162float(__float2bfloat16(f[j]));
    uint4 hu, lu;
    hu.x = pack_bf16x2(h[0], h[1]); hu.y = pack_bf16x2(h[2], h[3]);
    hu.z = pack_bf16x2(h[4], h[5]); hu.w = pack_bf16x2(h[6], h[7]);
    lu.x = pack_bf16x2(f[0]-h[0], f[1]-h[1]); lu.y = pack_bf16x2(f[2]-h[2], f[3]-h[3]);
    lu.z = pack_bf16x2(f[4]-h[4], f[5]-h[5]); lu.w = pack_bf16x2(f[6]-h[6], f[7]-h[7]);
    size_t rowb = ((size_t)kc * M + m) * 128;
    *(uint4*)((char*)o + swzs(rowb + (size_t)kin * 2))      = hu;
    *(uint4*)((char*)o + swzs(rowb + 64 + (size_t)kin * 2)) = lu;
}

// ---------------------------------------------------------------------------
// w[K][N] fp32 -> wT chunk-major hi/lo preswizzled: [kc][n][32h|32l].
// Block (32,8); blockIdx.y = kc (32 k = one chunk), blockIdx.x = n0/32.
// ---------------------------------------------------------------------------
__global__ void wsplit_chunk(const float* __restrict__ w, __nv_bfloat16* __restrict__ o,
                             int K, int N)
{
    __shared__ float t[32][33];
    int n0 = blockIdx.x * 32, k0 = blockIdx.y * 32;
    int tx = threadIdx.x, ty = threadIdx.y;
    for (int j = ty; j < 32; j += 8)
        t[j][tx] = w[(size_t)(k0 + j) * N + n0 + tx];
    __syncthreads();
    // thread (tx,ty): n = n0+tx, kin = ty*4 .. ty*4+3
    float f0 = t[ty * 4 + 0][tx], f1 = t[ty * 4 + 1][tx];
    float f2 = t[ty * 4 + 2][tx], f3 = t[ty * 4 + 3][tx];
    float h0 = __bfloat162float(__float2bfloat16(f0));
    float h1 = __bfloat162float(__float2bfloat16(f1));
    float h2 = __bfloat162float(__float2bfloat16(f2));
    float h3 = __bfloat162float(__float2bfloat16(f3));
    uint2 hu, lu;
    hu.x = pack_bf16x2(h0, h1); hu.y = pack_bf16x2(h2, h3);
    lu.x = pack_bf16x2(f0 - h0, f1 - h1); lu.y = pack_bf16x2(f2 - h2, f3 - h3);
    size_t rowb = ((size_t)blockIdx.y * N + n0 + tx) * 128;
    *(uint2*)((char*)o + swzs(rowb + (size_t)ty * 8))      = hu;
    *(uint2*)((char*)o + swzs(rowb + 64 + (size_t)ty * 8)) = lu;
}

// ---------------------------------------------------------------------------
// qkv fp32 -> Q (scaled) and K head-major hi/lo splits: [h][t][64] (unchanged)
// ---------------------------------------------------------------------------
__global__ void qk_split(const float* __restrict__ qkv,
                         __nv_bfloat16* __restrict__ qh, __nv_bfloat16* __restrict__ ql,
                         __nv_bfloat16* __restrict__ kh, __nv_bfloat16* __restrict__ kl)
{
    const float sc = 0.125f * 1.4426950408889634f;
    size_t i4 = ((size_t)blockIdx.x * blockDim.x + threadIdx.x) * 4;
    int d = (int)(i4 & 63);
    int t = (int)((i4 >> 6) & (TT - 1));
    int h = (int)(i4 >> 18);
    const float* qp = qkv + (size_t)t * (3 * DD) + h * HDIM + d;
    float4 q = *(const float4*)qp;
    float4 k = *(const float4*)(qp + DD);
    q.x *= sc; q.y *= sc; q.z *= sc; q.w *= sc;
    float qh0 = __bfloat162float(__float2bfloat16(q.x));
    float qh1 = __bfloat162float(__float2bfloat16(q.y));
    float qh2 = __bfloat162float(__float2bfloat16(q.z));
    float qh3 = __bfloat162float(__float2bfloat16(q.w));
    float kh0 = __bfloat162float(__float2bfloat16(k.x));
    float kh1 = __bfloat162float(__float2bfloat16(k.y));
    float kh2 = __bfloat162float(__float2bfloat16(k.z));
    float kh3 = __bfloat162float(__float2bfloat16(k.w));
    uint2 v;
    v.x = pack_bf16x2(qh0, qh1); v.y = pack_bf16x2(qh2, qh3);
    *(uint2*)(qh + i4) = v;
    v.x = pack_bf16x2(q.x - qh0, q.y - qh1); v.y = pack_bf16x2(q.z - qh2, q.w - qh3);
    *(uint2*)(ql + i4) = v;
    v.x = pack_bf16x2(kh0, kh1); v.y = pack_bf16x2(kh2, kh3);
    *(uint2*)(kh + i4) = v;
    v.x = pack_bf16x2(k.x - kh0, k.y - kh1); v.y = pack_bf16x2(k.z - kh2, k.w - kh3);
    *(uint2*)(kl + i4) = v;
}

// ---------------------------------------------------------------------------
// qkv V part -> transposed hi/lo: vt[h][d][t] (unchanged)
// ---------------------------------------------------------------------------
__global__ void vt_split(const float* __restrict__ qkv,
                         __nv_bfloat16* __restrict__ vth, __nv_bfloat16* __restrict__ vtl)
{
    __shared__ float sm[32][33];
    int t0 = blockIdx.x * 32, d0 = blockIdx.y * 32, h = blockIdx.z;
    int tx = threadIdx.x, ty = threadIdx.y;
    for (int j = ty; j < 32; j += 8)
        sm[j][tx] = qkv[(size_t)(t0 + j) * (3 * DD) + 2 * DD + h * HDIM + d0 + tx];
    __syncthreads();
    for (int j = ty; j < 32; j += 8) {
        float v = sm[tx][j];
        __nv_bfloat16 hh = __float2bfloat16(v);
        __nv_bfloat16 ll = __float2bfloat16(v - __bfloat162float(hh));
        size_t o = ((size_t)h * HDIM + d0 + j) * TT + t0 + tx;
        vth[o] = hh; vtl[o] = ll;
    }
}

// ---------------------------------------------------------------------------
// mma.sync bf16 split GEMM with cp.async.bulk stage loads.
// C[M,N] fp32 = A @ B^T; A/B given chunk-major hi/lo preswizzled.
// CTA 128x128, 8 warps (2m x 4n), warp 64x32, BK=32, double-buffered.
// Per chunk: 2 bulk copies of 16KB (A rows bm..bm+128, B rows bn..bn+128).
// mbarrier per stage; waits one-phase-deep everywhere.
// ---------------------------------------------------------------------------
#define CH_BYTES 16384               // 128 rows x 128B
#define STG_BYTES (2 * CH_BYTES)     // A + B
#define GSMEM (2 * STG_BYTES)        // 65536

__global__ __launch_bounds__(256, 2) void tc_gemm(
    const __nv_bfloat16* __restrict__ Ahl, const __nv_bfloat16* __restrict__ Bhl,
    float* __restrict__ C, int M, int N, int K)
{
    extern __shared__ __align__(1024) char dsm[];
    __shared__ __align__(8) uint64_t mbar_s[2];
    const uint32_t base = smem_u32(dsm);

    const int tid  = threadIdx.x;
    const int wid  = tid >> 5;
    const int lane = tid & 31;
    const int wm   = wid >> 2;
    const int wn   = wid & 3;
    const int bm   = blockIdx.y * 128, bn = blockIdx.x * 128;
    const int lrow = (lane & 7) + ((lane >> 3) & 1) * 8;
    const int lkof = (lane >> 4) * 8;

    if (tid == 0) {
        MBARRIER_INIT(smem_u32(&mbar_s[0]), 1);
        MBARRIER_INIT(smem_u32(&mbar_s[1]), 1);
    }
    __syncthreads();
    uint32_t mb0 = smem_u32(&mbar_s[0]);
    uint32_t mb1 = smem_u32(&mbar_s[1]);

    const int NCH = K / 32;

    auto issue = [&](int s, int t) {
        uint32_t m = s ? mb1 : mb0;
        MBARRIER_EXPECT_TX(m, STG_BYTES);
        const char* srcA = (const char*)Ahl + ((size_t)t * M + bm) * 128;
        const char* srcB = (const char*)Bhl + ((size_t)t * N + bn) * 128;
        uint32_t d = base + s * STG_BYTES;
        bulk_g2s(d,            srcA, CH_BYTES, m);
        bulk_g2s(d + CH_BYTES, srcB, CH_BYTES, m);
    };
    if (tid == 0) {
        issue(0, 0);
        if (NCH > 1) issue(1, 1);
    }

    float acc[4][4][4];
    #pragma unroll
    for (int mt = 0; mt < 4; mt++)
        #pragma unroll
        for (int nt = 0; nt < 4; nt++)
            #pragma unroll
            for (int c = 0; c < 4; c++) acc[mt][nt][c] = 0.f;

    int ph0 = 0, ph1 = 0;

    for (int t = 0; t < NCH; t++) {
        int s = t & 1;
        if (s == 0) { MBARRIER_WAIT_PARITY(mb0, ph0); ph0 ^= 1; }
        else        { MBARRIER_WAIT_PARITY(mb1, ph1); ph1 ^= 1; }

        uint32_t aB = base + s * STG_BYTES;
        uint32_t bB = aB + CH_BYTES;

        #pragma unroll
        for (int ks = 0; ks < 2; ks++) {
            const uint32_t kb = (uint32_t)(ks * 16 + lkof) * 2;

            uint32_t bh[4][2], bl[4][2];
            #pragma unroll
            for (int p = 0; p < 2; p++) {
                uint32_t ro = (uint32_t)(wn * 32 + p * 16 + lrow) * 128;
                uint32_t r0, r1, r2, r3;
                ldsm_x4(r0, r1, r2, r3, bB + swz(ro + kb));
                bh[p * 2][0] = r0; bh[p * 2][1] = r2;
                bh[p * 2 + 1][0] = r1; bh[p * 2 + 1][1] = r3;
                ldsm_x4(r0, r1, r2, r3, bB + swz(ro + 64 + kb));
                bl[p * 2][0] = r0; bl[p * 2][1] = r2;
                bl[p * 2 + 1][0] = r1; bl[p * 2 + 1][1] = r3;
            }

            #pragma unroll
            for (int mt = 0; mt < 4; mt++) {
                uint32_t ro = (uint32_t)(wm * 64 + mt * 16 + lrow) * 128;
                uint32_t ah0, ah1, ah2, ah3, al0, al1, al2, al3;
                ldsm_x4(ah0, ah1, ah2, ah3, aB + swz(ro + kb));
                ldsm_x4(al0, al1, al2, al3, aB + swz(ro + 64 + kb));
                #pragma unroll
                for (int nt = 0; nt < 4; nt++) {
                    float* c = acc[mt][nt];
                    mma16816(c[0], c[1], c[2], c[3], ah0, ah1, ah2, ah3,
                             bh[nt][0], bh[nt][1]);
                    mma16816(c[0], c[1], c[2], c[3], ah0, ah1, ah2, ah3,
                             bl[nt][0], bl[nt][1]);
                    mma16816(c[0], c[1], c[2], c[3], al0, al1, al2, al3,
                             bh[nt][0], bh[nt][1]);
                }
            }
        }
        __syncthreads();                 // all warps done reading stage s
        if (tid == 0 && t + 2 < NCH) issue(s, t + 2);
    }

    const int g  = lane >> 2;
    const int tg = lane & 3;
    #pragma unroll
    for (int mt = 0; mt < 4; mt++) {
        #pragma unroll
        for (int nt = 0; nt < 4; nt++) {
            int row = bm + wm * 64 + mt * 16 + g;
            int col = bn + wn * 32 + nt * 8 + tg * 2;
            float* c = acc[mt][nt];
            *(float2*)(C + (size_t)row * N + col)       = make_float2(c[0], c[1]);
            *(float2*)(C + (size_t)(row + 8) * N + col) = make_float2(c[2], c[3]);
        }
    }
}

// ---------------------------------------------------------------------------
// Flash attention on mma.sync bf16 (split) — unchanged from round 9 (passing).
// ---------------------------------------------------------------------------
#define RSB2 144
#define KMAT (64 * RSB2)
#define KSTG (4 * KMAT)
#define ASMEM (2 * KSTG)

__global__ __launch_bounds__(256, 1) void attn_mma(
    const __nv_bfloat16* __restrict__ Qh, const __nv_bfloat16* __restrict__ Ql,
    const __nv_bfloat16* __restrict__ Kh, const __nv_bfloat16* __restrict__ Kl,
    const __nv_bfloat16* __restrict__ Vth, const __nv_bfloat16* __restrict__ Vtl,
    float* __restrict__ out)
{
    extern __shared__ __align__(1024) char asmem[];
    const uint32_t base = smem_u32(asmem);

    const int h   = blockIdx.y;
    const int bx  = (gridDim.x - 1) - blockIdx.x;
    const int q0  = bx * 128;
    const int tid = threadIdx.x;
    const int w   = tid >> 5;
    const int lane = tid & 31;
    const int g   = lane >> 2;
    const int cq  = lane & 3;
    const int lrow = (lane & 7) + ((lane >> 3) & 1) * 8;
    const int lkof = (lane >> 4) * 8;

    {
        #pragma unroll
        for (int it = 0; it < 4; it++) {
            int slot = tid + it * 256;
            int row = slot >> 3, gg = slot & 7;
            size_t qo = ((size_t)h * TT + q0 + row) * HDIM + gg * 8;
            cp16(base + row * RSB2 + gg * 16,              Qh + qo);
            cp16(base + 128 * RSB2 + row * RSB2 + gg * 16, Ql + qo);
        }
        cp_commit();
        cp_wait<0>();
    }
    __syncthreads();
    uint32_t qh[4][4], ql[4][4];
    #pragma unroll
    for (int ks = 0; ks < 4; ks++) {
        uint32_t addr = base + (uint32_t)(w * 16 + lrow) * RSB2 + (uint32_t)(ks * 16 + lkof) * 2;
        ldsm_x4(qh[ks][0], qh[ks][1], qh[ks][2], qh[ks][3], addr);
        ldsm_x4(ql[ks][0], ql[ks][1], ql[ks][2], ql[ks][3], addr + 128 * RSB2);
    }
    __syncthreads();

    float o[8][4];
    #pragma unroll
    for (int dt = 0; dt < 8; dt++)
        #pragma unroll
        for (int c = 0; c < 4; c++) o[dt][c] = 0.f;
    float m0 = -INFINITY, m1 = -INFINITY, lp0 = 0.f, lp1 = 0.f;

    auto stage_kv = [&](int s, int k0) {
        uint32_t b = base + s * KSTG;
        #pragma unroll
        for (int it = 0; it < 2; it++) {
            int slot = tid + it * 256;
            int row = slot >> 3, gg = slot & 7;
            uint32_t so = (uint32_t)(row * RSB2 + gg * 16);
            size_t ko = ((size_t)h * TT + k0 + row) * HDIM + gg * 8;
            size_t vo = ((size_t)h * HDIM + row) * TT + k0 + gg * 8;
            cp16(b + so,            Kh + ko);
            cp16(b + KMAT + so,     Kl + ko);
            cp16(b + 2 * KMAT + so, Vth + vo);
            cp16(b + 3 * KMAT + so, Vtl + vo);
        }
        cp_commit();
    };

    const int ntiles = (q0 + 128) >> 6;
    stage_kv(0, 0);

    const int row0 = q0 + w * 16 + g;

    for (int t = 0; t < ntiles; t++) {
        const int k0 = t << 6;
        if (t + 1 < ntiles) {
            stage_kv((t + 1) & 1, (t + 1) * 64);
            cp_wait<1>();
        } else {
            cp_wait<0>();
        }
        __syncthreads();

        uint32_t sb = base + (t & 1) * KSTG;

        float s[8][4];
        #pragma unroll
        for (int nt = 0; nt < 8; nt++)
            #pragma unroll
            for (int c = 0; c < 4; c++) s[nt][c] = 0.f;

        #pragma unroll
        for (int ks = 0; ks < 4; ks++) {
            const uint32_t kb = (uint32_t)(ks * 16 + lkof) * 2;
            #pragma unroll
            for (int p = 0; p < 4; p++) {
                uint32_t roff = (uint32_t)(p * 16 + lrow) * RSB2 + kb;
                uint32_t r0, r1, r2, r3, u0, u1, u2, u3;
                ldsm_x4(r0, r1, r2, r3, sb + roff);
                ldsm_x4(u0, u1, u2, u3, sb + KMAT + roff);
                float* s0 = s[2 * p];
                float* s1 = s[2 * p + 1];
                mma16816(s0[0], s0[1], s0[2], s0[3], qh[ks][0], qh[ks][1], qh[ks][2], qh[ks][3], r0, r2);
                mma16816(s0[0], s0[1], s0[2], s0[3], qh[ks][0], qh[ks][1], qh[ks][2], qh[ks][3], u0, u2);
                mma16816(s0[0], s0[1], s0[2], s0[3], ql[ks][0], ql[ks][1], ql[ks][2], ql[ks][3], r0, r2);
                mma16816(s1[0], s1[1], s1[2], s1[3], qh[ks][0], qh[ks][1], qh[ks][2], qh[ks][3], r1, r3);
                mma16816(s1[0], s1[1], s1[2], s1[3], qh[ks][0], qh[ks][1], qh[ks][2], qh[ks][3], u1, u3);
                mma16816(s1[0], s1[1], s1[2], s1[3], ql[ks][0], ql[ks][1], ql[ks][2], ql[ks][3], r1, r3);
            }
        }

        if (k0 + 64 > q0) {
            #pragma unroll
            for (int nt = 0; nt < 8; nt++) {
                int col = k0 + nt * 8 + 2 * cq;
                if (col     > row0)     s[nt][0] = -INFINITY;
                if (col + 1 > row0)     s[nt][1] = -INFINITY;
                if (col     > row0 + 8) s[nt][2] = -INFINITY;
                if (col + 1 > row0 + 8) s[nt][3] = -INFINITY;
            }
        }

        float mx0 = -INFINITY, mx1 = -INFINITY;
        #pragma unroll
        for (int nt = 0; nt < 8; nt++) {
            mx0 = fmaxf(mx0, fmaxf(s[nt][0], s[nt][1]));
            mx1 = fmaxf(mx1, fmaxf(s[nt][2], s[nt][3]));
        }
        mx0 = fmaxf(mx0, __shfl_xor_sync(0xffffffffu, mx0, 1));
        mx0 = fmaxf(mx0, __shfl_xor_sync(0xffffffffu, mx0, 2));
        mx1 = fmaxf(mx1, __shfl_xor_sync(0xffffffffu, mx1, 1));
        mx1 = fmaxf(mx1, __shfl_xor_sync(0xffffffffu, mx1, 2));
        float mn0 = fmaxf(m0, mx0), mn1 = fmaxf(m1, mx1);
        float cf0 = fast_exp2(m0 - mn0), cf1 = fast_exp2(m1 - mn1);
        m0 = mn0; m1 = mn1;
        lp0 *= cf0; lp1 *= cf1;
        #pragma unroll
        for (int dt = 0; dt < 8; dt++) {
            o[dt][0] *= cf0; o[dt][1] *= cf0;
            o[dt][2] *= cf1; o[dt][3] *= cf1;
        }

        uint32_t pah0[8], pah1[8], pal0[8], pal1[8];
        #pragma unroll
        for (int nt = 0; nt < 8; nt++) {
            float p0 = fast_exp2(s[nt][0] - m0);
            float p1 = fast_exp2(s[nt][1] - m0);
            float p2 = fast_exp2(s[nt][2] - m1);
            float p3 = fast_exp2(s[nt][3] - m1);
            lp0 += p0 + p1; lp1 += p2 + p3;
            float h0 = __bfloat162float(__float2bfloat16(p0));
            float h1 = __bfloat162float(__float2bfloat16(p1));
            float h2 = __bfloat162float(__float2bfloat16(p2));
            float h3 = __bfloat162float(__float2bfloat16(p3));
            pah0[nt] = pack_bf16x2(h0, h1);
            pah1[nt] = pack_bf16x2(h2, h3);
            pal0[nt] = pack_bf16x2(p0 - h0, p1 - h1);
            pal1[nt] = pack_bf16x2(p2 - h2, p3 - h3);
        }

        #pragma unroll
        for (int kk = 0; kk < 4; kk++) {
            uint32_t ah0 = pah0[2 * kk], ah1 = pah1[2 * kk];
            uint32_t ah2 = pah0[2 * kk + 1], ah3 = pah1[2 * kk + 1];
            uint32_t al0 = pal0[2 * kk], al1 = pal1[2 * kk];
            uint32_t al2 = pal0[2 * kk + 1], al3 = pal1[2 * kk + 1];
            const uint32_t kb = (uint32_t)(kk * 16 + lkof) * 2;
            #pragma unroll
            for (int dp = 0; dp < 4; dp++) {
                uint32_t roff = (uint32_t)(dp * 16 + lrow) * RSB2 + kb;
                uint32_t v0, v1, v2, v3, x0, x1, x2, x3;
                ldsm_x4(v0, v1, v2, v3, sb + 2 * KMAT + roff);
                ldsm_x4(x0, x1, x2, x3, sb + 3 * KMAT + roff);
                float* oa = o[2 * dp];
                float* ob = o[2 * dp + 1];
                mma16816(oa[0], oa[1], oa[2], oa[3], ah0, ah1, ah2, ah3, v0, v2);
                mma16816(oa[0], oa[1], oa[2], oa[3], ah0, ah1, ah2, ah3, x0, x2);
                mma16816(oa[0], oa[1], oa[2], oa[3], al0, al1, al2, al3, v0, v2);
                mma16816(ob[0], ob[1], ob[2], ob[3], ah0, ah1, ah2, ah3, v1, v3);
                mma16816(ob[0], ob[1], ob[2], ob[3], ah0, ah1, ah2, ah3, x1, x3);
                mma16816(ob[0], ob[1], ob[2], ob[3], al0, al1, al2, al3, v1, v3);
            }
        }
        __syncthreads();
    }

    lp0 += __shfl_xor_sync(0xffffffffu, lp0, 1);
    lp0 += __shfl_xor_sync(0xffffffffu, lp0, 2);
    lp1 += __shfl_xor_sync(0xffffffffu, lp1, 1);
    lp1 += __shfl_xor_sync(0xffffffffu, lp1, 2);
    float inv0 = 1.0f / lp0, inv1 = 1.0f / lp1;
    #pragma unroll
    for (int dt = 0; dt < 8; dt++) {
        int col = h * HDIM + dt * 8 + 2 * cq;
        *(float2*)(out + (size_t)row0 * DD + col) =
            make_float2(o[dt][0] * inv0, o[dt][1] * inv0);
        *(float2*)(out + (size_t)(row0 + 8) * DD + col) =
            make_float2(o[dt][2] * inv1, o[dt][3] * inv1);
    }
}

// ---------------------------------------------------------------------------
extern "C" void kernel_launch(void* const* d_in, const int* in_sizes, int n_in,
                              void* d_out, int out_size)
{
    const float* x    = (const float*)d_in[0];
    const float* wqkv = (const float*)d_in[1];
    const float* wout = (const float*)d_in[2];
    float* out = (float*)d_out;

    float *qkv, *att;
    __nv_bfloat16 *xhl, *w1hl, *w2hl, *ahl;
    __nv_bfloat16 *qh, *ql, *kh, *kl, *vth, *vtl;
    cudaGetSymbolAddress((void**)&qkv,  g_qkv);
    cudaGetSymbolAddress((void**)&att,  g_att);
    cudaGetSymbolAddress((void**)&xhl,  g_xhl);
    cudaGetSymbolAddress((void**)&w1hl, g_w1hl);
    cudaGetSymbolAddress((void**)&w2hl, g_w2hl);
    cudaGetSymbolAddress((void**)&ahl,  g_ahl);
    cudaGetSymbolAddress((void**)&qh,   g_qh);
    cudaGetSymbolAddress((void**)&ql,   g_ql);
    cudaGetSymbolAddress((void**)&kh,   g_kh);
    cudaGetSymbolAddress((void**)&kl,   g_kl);
    cudaGetSymbolAddress((void**)&vth,  g_vth);
    cudaGetSymbolAddress((void**)&vtl,  g_vtl);

    cudaFuncSetAttribute(tc_gemm,  cudaFuncAttributeMaxDynamicSharedMemorySize, GSMEM);
    cudaFuncSetAttribute(attn_mma, cudaFuncAttributeMaxDynamicSharedMemorySize, ASMEM);

    // prep: chunk-major hi/lo splits (activations + weights)
    split_chunk<<<(TT * DD / 8 + 255) / 256, 256>>>(x, xhl, TT, DD);
    wsplit_chunk<<<dim3(3 * DD / 32, DD / 32), dim3(32, 8)>>>(wqkv, w1hl, DD, 3 * DD);
    wsplit_chunk<<<dim3(DD / 32, DD / 32), dim3(32, 8)>>>(wout, w2hl, DD, DD);

    // 1) QKV projection (tensor cores, bulk-copy pipeline)
    tc_gemm<<<dim3(3 * DD / 128, TT / 128), 256, GSMEM>>>(xhl, w1hl, qkv, TT, 3 * DD, DD);

    // attention operand prep
    qk_split<<<(NH * TT * HDIM / 4 + 255) / 256, 256>>>(qkv, qh, ql, kh, kl);
    vt_split<<<dim3(TT / 32, HDIM / 32, NH), dim3(32, 8)>>>(qkv, vth, vtl);

    // 2) causal attention (tensor cores)
    attn_mma<<<dim3(TT / 128, NH), 256, ASMEM>>>(qh, ql, kh, kl, vth, vtl, att);

    // split attention output for GEMM2 (chunk-major)
    split_chunk<<<(TT * DD / 8 + 255) / 256, 256>>>(att, ahl, TT, DD);

    // 3) output projection (tensor cores)
    tc_gemm<<<dim3(DD / 128, TT / 128), 256, GSMEM>>>(ahl, w2hl, out, TT, DD, DD);
}

// round 11
// speedup vs baseline: 7.8718x; 1.0607x over previous
#include <cuda_runtime.h>
#include <cuda_bf16.h>
#include <math.h>
#include <stdint.h>

#define TT 4096
#define DD 1024
#define NH 16
#define HDIM 64

// ---------------------------------------------------------------------------
// Scratch (allocation-free rule: device globals). 16B-aligned.
// GEMM operands chunk-major hi/lo interleaved, SW128-preswizzled:
//   [kc][row][32 hi bf16 | 32 lo bf16] (128B rows, kc = K/32)
// Attention: Q as preswizzled 128B rows [h][t][64] (hi and lo buffers);
// K/V packed per (head, 64-key tile) as one 32KB block: Kh|Kl|Vth|Vtl,
// each 64 rows x 128B preswizzled (Vt rows are d-major: [d][key]).
// ---------------------------------------------------------------------------
__device__ __align__(16) float g_qkv[(size_t)TT * 3 * DD];   // 48 MB
__device__ __align__(16) __nv_bfloat16 g_xhl[(size_t)TT * DD * 2];
__device__ __align__(16) __nv_bfloat16 g_w1hl[(size_t)3 * DD * DD * 2];
__device__ __align__(16) __nv_bfloat16 g_w2hl[(size_t)DD * DD * 2];
__device__ __align__(16) __nv_bfloat16 g_ahl[(size_t)TT * DD * 2];
__device__ __align__(16) __nv_bfloat16 g_qph[(size_t)NH * TT * HDIM];
__device__ __align__(16) __nv_bfloat16 g_qpl[(size_t)NH * TT * HDIM];
__device__ __align__(16) __nv_bfloat16 g_kvp[(size_t)NH * (TT / 64) * 16384]; // 32MB (32KB/block)

// ---------------------------------------------------------------------------
// PTX helpers
// ---------------------------------------------------------------------------
__device__ __forceinline__ uint32_t smem_u32(const void* p) {
    uint32_t a;
    asm("{ .reg .u64 t; cvta.to.shared.u64 t, %1; cvt.u32.u64 %0, t; }" : "=r"(a) : "l"(p));
    return a;
}
__device__ __forceinline__ void ldsm_x4(uint32_t& r0, uint32_t& r1, uint32_t& r2, uint32_t& r3,
                                        uint32_t addr) {
    asm volatile("ldmatrix.sync.aligned.m8n8.x4.shared.b16 {%0,%1,%2,%3}, [%4];"
                 : "=r"(r0), "=r"(r1), "=r"(r2), "=r"(r3) : "r"(addr));
}
// NOTE: not volatile — pure register computation; lets ptxas schedule freely.
__device__ __forceinline__ void mma16816(float& c0, float& c1, float& c2, float& c3,
                                         uint32_t a0, uint32_t a1, uint32_t a2, uint32_t a3,
                                         uint32_t b0, uint32_t b1) {
    asm("mma.sync.aligned.m16n8k16.row.col.f32.bf16.bf16.f32 "
        "{%0,%1,%2,%3}, {%4,%5,%6,%7}, {%8,%9}, {%0,%1,%2,%3};"
        : "+f"(c0), "+f"(c1), "+f"(c2), "+f"(c3)
        : "r"(a0), "r"(a1), "r"(a2), "r"(a3), "r"(b0), "r"(b1));
}
__device__ __forceinline__ void bulk_g2s(uint32_t dst, const void* src, uint32_t bytes,
                                         uint32_t mbar) {
    asm volatile("cp.async.bulk.shared::cluster.global.mbarrier::complete_tx::bytes "
                 "[%0], [%1], %2, [%3];"
                 :: "r"(dst), "l"(src), "r"(bytes), "r"(mbar) : "memory");
}
#define MBARRIER_INIT(mb, c) \
    asm volatile("mbarrier.init.shared.b64 [%0], %1;" :: "r"((uint32_t)(mb)), "r"((uint32_t)(c)) : "memory")
#define MBARRIER_EXPECT_TX(mb, bytes) \
    asm volatile("mbarrier.arrive.expect_tx.shared.b64 _, [%0], %1;" \
                 :: "r"((uint32_t)(mb)), "r"((uint32_t)(bytes)) : "memory")
#define MBARRIER_WAIT_PARITY(mb, ph) do { \
    uint32_t _m = (uint32_t)(mb), _p = (uint32_t)(ph), _d; \
    asm volatile("{ .reg .pred p; mbarrier.try_wait.parity.acquire.cta.shared::cta.b64 p, [%1], %2; " \
                 "selp.b32 %0, 1, 0, p; }" : "=r"(_d) : "r"(_m), "r"(_p) : "memory"); \
    if (!_d) { \
        asm volatile("{ .reg .pred P1; WL_%=: mbarrier.try_wait.parity.acquire.cta.shared::cta.b64 P1, [%0], %1, 0x989680; " \
                     "@P1 bra.uni WD_%=; bra.uni WL_%=; WD_%=: }" :: "r"(_m), "r"(_p) : "memory"); \
    } \
} while (0)

__device__ __forceinline__ float fast_exp2(float x) {
    float y;
    asm("ex2.approx.ftz.f32 %0, %1;" : "=f"(y) : "f"(x));
    return y;
}
__device__ __forceinline__ uint32_t pack_bf16x2(float a, float b) {
    __nv_bfloat162 t = __floats2bfloat162_rn(a, b);
    return *reinterpret_cast<uint32_t*>(&t);
}
__device__ __forceinline__ uint32_t swz(uint32_t o)  { return o ^ ((o >> 3) & 0x70); }
__device__ __forceinline__ size_t   swzs(size_t o)   { return o ^ ((o >> 3) & 0x70); }

// split 16 fp32 into hi/lo bf16 packed uint4 pairs (register-only)
__device__ __forceinline__ void split16(const float (&f)[16],
                                        uint4& h0, uint4& h1, uint4& l0, uint4& l1)
{
    float hh[16];
    #pragma unroll
    for (int i = 0; i < 16; i++) hh[i] = __bfloat162float(__float2bfloat16(f[i]));
    h0 = make_uint4(pack_bf16x2(hh[0], hh[1]),  pack_bf16x2(hh[2], hh[3]),
                    pack_bf16x2(hh[4], hh[5]),  pack_bf16x2(hh[6], hh[7]));
    h1 = make_uint4(pack_bf16x2(hh[8], hh[9]),  pack_bf16x2(hh[10], hh[11]),
                    pack_bf16x2(hh[12], hh[13]), pack_bf16x2(hh[14], hh[15]));
    l0 = make_uint4(pack_bf16x2(f[0]-hh[0], f[1]-hh[1]),   pack_bf16x2(f[2]-hh[2], f[3]-hh[3]),
                    pack_bf16x2(f[4]-hh[4], f[5]-hh[5]),   pack_bf16x2(f[6]-hh[6], f[7]-hh[7]));
    l1 = make_uint4(pack_bf16x2(f[8]-hh[8], f[9]-hh[9]),   pack_bf16x2(f[10]-hh[10], f[11]-hh[11]),
                    pack_bf16x2(f[12]-hh[12], f[13]-hh[13]), pack_bf16x2(f[14]-hh[14], f[15]-hh[15]));
}

// ---------------------------------------------------------------------------
// fp32 [M][K] -> chunk-major hi/lo preswizzled (unchanged from round 10)
// ---------------------------------------------------------------------------
__global__ void split_chunk(const float* __restrict__ s, __nv_bfloat16* __restrict__ o,
                            int M, int K)
{
    size_t i8 = ((size_t)blockIdx.x * blockDim.x + threadIdx.x) * 8;
    if (i8 >= (size_t)M * K) return;
    int m  = (int)(i8 / K);
    int k  = (int)(i8 % K);
    int kc = k >> 5, kin = k & 31;
    float4 v0 = *(const float4*)(s + i8);
    float4 v1 = *(const float4*)(s + i8 + 4);
    float f[8] = {v0.x, v0.y, v0.z, v0.w, v1.x, v1.y, v1.z, v1.w};
    float h[8];
    #pragma unroll
    for (int j = 0; j < 8; j++) h[j] = __bfloat162float(__float2bfloat16(f[j]));
    uint4 hu, lu;
    hu.x = pack_bf16x2(h[0], h[1]); hu.y = pack_bf16x2(h[2], h[3]);
    hu.z = pack_bf16x2(h[4], h[5]); hu.w = pack_bf16x2(h[6], h[7]);
    lu.x = pack_bf16x2(f[0]-h[0], f[1]-h[1]); lu.y = pack_bf16x2(f[2]-h[2], f[3]-h[3]);
    lu.z = pack_bf16x2(f[4]-h[4], f[5]-h[5]); lu.w = pack_bf16x2(f[6]-h[6], f[7]-h[7]);
    size_t rowb = ((size_t)kc * M + m) * 128;
    *(uint4*)((char*)o + swzs(rowb + (size_t)kin * 2))      = hu;
    *(uint4*)((char*)o + swzs(rowb + 64 + (size_t)kin * 2)) = lu;
}

// ---------------------------------------------------------------------------
// w[K][N] fp32 -> wT chunk-major hi/lo preswizzled (unchanged)
// ---------------------------------------------------------------------------
__global__ void wsplit_chunk(const float* __restrict__ w, __nv_bfloat16* __restrict__ o,
                             int K, int N)
{
    __shared__ float t[32][33];
    int n0 = blockIdx.x * 32, k0 = blockIdx.y * 32;
    int tx = threadIdx.x, ty = threadIdx.y;
    for (int j = ty; j < 32; j += 8)
        t[j][tx] = w[(size_t)(k0 + j) * N + n0 + tx];
    __syncthreads();
    float f0 = t[ty * 4 + 0][tx], f1 = t[ty * 4 + 1][tx];
    float f2 = t[ty * 4 + 2][tx], f3 = t[ty * 4 + 3][tx];
    float h0 = __bfloat162float(__float2bfloat16(f0));
    float h1 = __bfloat162float(__float2bfloat16(f1));
    float h2 = __bfloat162float(__float2bfloat16(f2));
    float h3 = __bfloat162float(__float2bfloat16(f3));
    uint2 hu, lu;
    hu.x = pack_bf16x2(h0, h1); hu.y = pack_bf16x2(h2, h3);
    lu.x = pack_bf16x2(f0 - h0, f1 - h1); lu.y = pack_bf16x2(f2 - h2, f3 - h3);
    size_t rowb = ((size_t)blockIdx.y * N + n0 + tx) * 128;
    *(uint2*)((char*)o + swzs(rowb + (size_t)ty * 8))      = hu;
    *(uint2*)((char*)o + swzs(rowb + 64 + (size_t)ty * 8)) = lu;
}

// ---------------------------------------------------------------------------
// kv_pack: qkv fp32 -> Q preswizzled rows (scaled, hi/lo) + 32KB K/V blocks.
// One block per (64-key tile, head). 256 threads.
// ---------------------------------------------------------------------------
__global__ __launch_bounds__(256) void kv_pack(
    const float* __restrict__ qkv,
    __nv_bfloat16* __restrict__ qph, __nv_bfloat16* __restrict__ qpl,
    __nv_bfloat16* __restrict__ kvp)
{
    __shared__ float sv[64][68];
    const int nt = blockIdx.x, h = blockIdx.y;
    const int k0 = nt * 64;
    const int tid = threadIdx.x;
    const int r  = tid >> 2;            // row within tile 0..63
    const int d0 = (tid & 3) * 16;      // dim quarter
    const float sc = 0.125f * 1.4426950408889634f;

    const float* rowp = qkv + (size_t)(k0 + r) * (3 * DD) + h * HDIM + d0;
    float qf[16], kf[16];
    #pragma unroll
    for (int i = 0; i < 4; i++) {
        float4 q = *(const float4*)(rowp + 4 * i);
        float4 k = *(const float4*)(rowp + DD + 4 * i);
        float4 v = *(const float4*)(rowp + 2 * DD + 4 * i);
        qf[4*i+0] = q.x * sc; qf[4*i+1] = q.y * sc; qf[4*i+2] = q.z * sc; qf[4*i+3] = q.w * sc;
        kf[4*i+0] = k.x; kf[4*i+1] = k.y; kf[4*i+2] = k.z; kf[4*i+3] = k.w;
        sv[r][d0 + 4*i + 0] = v.x; sv[r][d0 + 4*i + 1] = v.y;
        sv[r][d0 + 4*i + 2] = v.z; sv[r][d0 + 4*i + 3] = v.w;
    }

    uint4 h0, h1, l0, l1;
    // Q rows
    split16(qf, h0, h1, l0, l1);
    size_t qrow = ((size_t)h * TT + k0 + r) * 128;
    *(uint4*)((char*)qph + swzs(qrow + (size_t)d0 * 2))      = h0;
    *(uint4*)((char*)qph + swzs(qrow + (size_t)d0 * 2 + 16)) = h1;
    *(uint4*)((char*)qpl + swzs(qrow + (size_t)d0 * 2))      = l0;
    *(uint4*)((char*)qpl + swzs(qrow + (size_t)d0 * 2 + 16)) = l1;
    // K rows
    split16(kf, h0, h1, l0, l1);
    size_t kvb = (size_t)(h * (TT / 64) + nt) * 32768;
    size_t kr = (size_t)r * 128 + (size_t)d0 * 2;
    *(uint4*)((char*)kvp + kvb + swzs(kr))             = h0;
    *(uint4*)((char*)kvp + kvb + swzs(kr + 16))        = h1;
    *(uint4*)((char*)kvp + kvb + 8192 + swzs(kr))      = l0;
    *(uint4*)((char*)kvp + kvb + 8192 + swzs(kr + 16)) = l1;

    __syncthreads();
    // V transposed rows: row = d (tid>>2), cols = keys
    {
        const int d  = tid >> 2;
        const int c0 = (tid & 3) * 16;
        float vf[16];
        #pragma unroll
        for (int i = 0; i < 16; i++) vf[i] = sv[c0 + i][d];
        split16(vf, h0, h1, l0, l1);
        size_t vr = (size_t)d * 128 + (size_t)c0 * 2;
        *(uint4*)((char*)kvp + kvb + 16384 + swzs(vr))      = h0;
        *(uint4*)((char*)kvp + kvb + 16384 + swzs(vr + 16)) = h1;
        *(uint4*)((char*)kvp + kvb + 24576 + swzs(vr))      = l0;
        *(uint4*)((char*)kvp + kvb + 24576 + swzs(vr + 16)) = l1;
    }
}

// ---------------------------------------------------------------------------
// Persistent mma.sync bf16 split GEMM with bulk-copy stages.
// grid <= total tiles; each CTA loops tiles with a flattened chunk counter.
// NCH = K/32 is even, so stage parity stays consistent across tiles; chunks
// t+2 issued after the per-chunk sync roll seamlessly into the next tile.
// ---------------------------------------------------------------------------
#define CH_BYTES 16384
#define STG_BYTES (2 * CH_BYTES)
#define GSMEM (2 * STG_BYTES)

__global__ __launch_bounds__(256, 2) void tc_gemm(
    const __nv_bfloat16* __restrict__ Ahl, const __nv_bfloat16* __restrict__ Bhl,
    float* __restrict__ C, int M, int N, int K)
{
    extern __shared__ __align__(1024) char dsm[];
    __shared__ __align__(8) uint64_t mbar_s[2];
    const uint32_t base = smem_u32(dsm);

    const int tid  = threadIdx.x;
    const int wid  = tid >> 5;
    const int lane = tid & 31;
    const int wm   = wid >> 2;
    const int wn   = wid & 3;
    const int lrow = (lane & 7) + ((lane >> 3) & 1) * 8;
    const int lkof = (lane >> 4) * 8;
    const int nx   = N >> 7;
    const int total = (M >> 7) * nx;
    const int NCH  = K / 32;

    if (tid == 0) {
        MBARRIER_INIT(smem_u32(&mbar_s[0]), 1);
        MBARRIER_INIT(smem_u32(&mbar_s[1]), 1);
    }
    __syncthreads();
    uint32_t mb0 = smem_u32(&mbar_s[0]);
    uint32_t mb1 = smem_u32(&mbar_s[1]);

    // flattened chunk issue: qi = myTileOrdinal*NCH + chunk
    auto issue = [&](int qi) {
        int k   = qi / NCH;
        int bid = blockIdx.x + k * gridDim.x;
        if (bid >= total) return;
        int chunk = qi - k * NCH;
        int s = qi & 1;
        int tbm = (bid / nx) * 128, tbn = (bid % nx) * 128;
        uint32_t m = s ? mb1 : mb0;
        MBARRIER_EXPECT_TX(m, STG_BYTES);
        uint32_t d = base + s * STG_BYTES;
        bulk_g2s(d,            (const char*)Ahl + ((size_t)chunk * M + tbm) * 128, CH_BYTES, m);
        bulk_g2s(d + CH_BYTES, (const char*)Bhl + ((size_t)chunk * N + tbn) * 128, CH_BYTES, m);
    };
    if (tid == 0) { issue(0); issue(1); }

    int ph0 = 0, ph1 = 0;
    int myk = 0;
    for (int bid = blockIdx.x; bid < total; bid += gridDim.x, myk++) {
        const int bm = (bid / nx) * 128, bn = (bid % nx) * 128;

        float acc[4][4][4];
        #pragma unroll
        for (int mt = 0; mt < 4; mt++)
            #pragma unroll
            for (int nt = 0; nt < 4; nt++)
                #pragma unroll
                for (int c = 0; c < 4; c++) acc[mt][nt][c] = 0.f;

        for (int t = 0; t < NCH; t++) {
            int s = t & 1;   // myk*NCH even -> parity matches qi
            if (s == 0) { MBARRIER_WAIT_PARITY(mb0, ph0); ph0 ^= 1; }
            else        { MBARRIER_WAIT_PARITY(mb1, ph1); ph1 ^= 1; }

            uint32_t aB = base + s * STG_BYTES;
            uint32_t bB = aB + CH_BYTES;

            #pragma unroll
            for (int ks = 0; ks < 2; ks++) {
                const uint32_t kb = (uint32_t)(ks * 16 + lkof) * 2;

                uint32_t bh[4][2], bl[4][2];
                #pragma unroll
                for (int p = 0; p < 2; p++) {
                    uint32_t ro = (uint32_t)(wn * 32 + p * 16 + lrow) * 128;
                    uint32_t r0, r1, r2, r3;
                    ldsm_x4(r0, r1, r2, r3, bB + swz(ro + kb));
                    bh[p * 2][0] = r0; bh[p * 2][1] = r2;
                    bh[p * 2 + 1][0] = r1; bh[p * 2 + 1][1] = r3;
                    ldsm_x4(r0, r1, r2, r3, bB + swz(ro + 64 + kb));
                    bl[p * 2][0] = r0; bl[p * 2][1] = r2;
                    bl[p * 2 + 1][0] = r1; bl[p * 2 + 1][1] = r3;
                }

                #pragma unroll
                for (int mt = 0; mt < 4; mt++) {
                    uint32_t ro = (uint32_t)(wm * 64 + mt * 16 + lrow) * 128;
                    uint32_t ah0, ah1, ah2, ah3, al0, al1, al2, al3;
                    ldsm_x4(ah0, ah1, ah2, ah3, aB + swz(ro + kb));
                    ldsm_x4(al0, al1, al2, al3, aB + swz(ro + 64 + kb));
                    #pragma unroll
                    for (int nt = 0; nt < 4; nt++) {
                        float* c = acc[mt][nt];
                        mma16816(c[0], c[1], c[2], c[3], ah0, ah1, ah2, ah3,
                                 bh[nt][0], bh[nt][1]);
                        mma16816(c[0], c[1], c[2], c[3], ah0, ah1, ah2, ah3,
                                 bl[nt][0], bl[nt][1]);
                        mma16816(c[0], c[1], c[2], c[3], al0, al1, al2, al3,
                                 bh[nt][0], bh[nt][1]);
                    }
                }
            }
            __syncthreads();
            if (tid == 0) issue(myk * NCH + t + 2);
        }

        const int g  = lane >> 2;
        const int tg = lane & 3;
        #pragma unroll
        for (int mt = 0; mt < 4; mt++) {
            #pragma unroll
            for (int nt = 0; nt < 4; nt++) {
                int row = bm + wm * 64 + mt * 16 + g;
                int col = bn + wn * 32 + nt * 8 + tg * 2;
                float* c = acc[mt][nt];
                *(float2*)(C + (size_t)row * N + col)       = make_float2(c[0], c[1]);
                *(float2*)(C + (size_t)(row + 8) * N + col) = make_float2(c[2], c[3]);
            }
        }
    }
}

// ---------------------------------------------------------------------------
// Flash attention, mma.sync bf16 split, bulk-copy K/V stages (3 deep).
// smem: [0,32KB) Q hi|lo; stages s at 32KB + s*32KB (Kh|Kl|Vth|Vtl, 8KB each).
// Epilogue writes chunk-major split ahl directly.
// ---------------------------------------------------------------------------
#define KV_BYTES 32768
#define ASMEM (32768 + 3 * KV_BYTES)   // 131072

__global__ __launch_bounds__(256, 1) void attn_mma(
    const __nv_bfloat16* __restrict__ Qph, const __nv_bfloat16* __restrict__ Qpl,
    const __nv_bfloat16* __restrict__ Kvp, __nv_bfloat16* __restrict__ Ahl)
{
    extern __shared__ __align__(1024) char asmem[];
    __shared__ __align__(8) uint64_t mbar_s[4];
    const uint32_t base = smem_u32(asmem);

    const int h   = blockIdx.y;
    const int bx  = (gridDim.x - 1) - blockIdx.x;
    const int q0  = bx * 128;
    const int tid = threadIdx.x;
    const int w   = tid >> 5;
    const int lane = tid & 31;
    const int g   = lane >> 2;
    const int cq  = lane & 3;
    const int lrow = (lane & 7) + ((lane >> 3) & 1) * 8;
    const int lkof = (lane >> 4) * 8;
    const int ntiles = (q0 + 128) >> 6;

    if (tid == 0) {
        #pragma unroll
        for (int j = 0; j < 4; j++) MBARRIER_INIT(smem_u32(&mbar_s[j]), 1);
    }
    __syncthreads();
    uint32_t mbq = smem_u32(&mbar_s[3]);
    uint32_t mb0 = smem_u32(&mbar_s[0]);
    uint32_t mb1 = smem_u32(&mbar_s[1]);
    uint32_t mb2 = smem_u32(&mbar_s[2]);

    auto issue_kv = [&](int s, int tt) {
        uint32_t m = (s == 0) ? mb0 : (s == 1) ? mb1 : mb2;
        MBARRIER_EXPECT_TX(m, KV_BYTES);
        bulk_g2s(base + 32768 + s * KV_BYTES,
                 (const char*)Kvp + (size_t)(h * (TT / 64) + tt) * KV_BYTES,
                 KV_BYTES, m);
    };

    if (tid == 0) {
        MBARRIER_EXPECT_TX(mbq, 32768);
        bulk_g2s(base,         (const char*)Qph + ((size_t)h * TT + q0) * 128, 16384, mbq);
        bulk_g2s(base + 16384, (const char*)Qpl + ((size_t)h * TT + q0) * 128, 16384, mbq);
        #pragma unroll
        for (int j = 0; j < 3; j++)
            if (j < ntiles) issue_kv(j, j);
    }

    // Q fragments
    MBARRIER_WAIT_PARITY(mbq, 0);
    uint32_t qh[4][4], ql[4][4];
    #pragma unroll
    for (int ks = 0; ks < 4; ks++) {
        uint32_t ro = (uint32_t)(w * 16 + lrow) * 128;
        uint32_t kb = (uint32_t)(ks * 16 + lkof) * 2;
        ldsm_x4(qh[ks][0], qh[ks][1], qh[ks][2], qh[ks][3], base + swz(ro + kb));
        ldsm_x4(ql[ks][0], ql[ks][1], ql[ks][2], ql[ks][3], base + 16384 + swz(ro + kb));
    }

    float o[8][4];
    #pragma unroll
    for (int dt = 0; dt < 8; dt++)
        #pragma unroll
        for (int c = 0; c < 4; c++) o[dt][c] = 0.f;
    float m0 = -INFINITY, m1 = -INFINITY, lp0 = 0.f, lp1 = 0.f;

    const int row0 = q0 + w * 16 + g;
    int ph0 = 0, ph1 = 0, ph2 = 0;
    int s = 0;

    for (int t = 0; t < ntiles; t++) {
        const int k0 = t << 6;
        if (s == 0) { MBARRIER_WAIT_PARITY(mb0, ph0); ph0 ^= 1; }
        else if (s == 1) { MBARRIER_WAIT_PARITY(mb1, ph1); ph1 ^= 1; }
        else { MBARRIER_WAIT_PARITY(mb2, ph2); ph2 ^= 1; }

        uint32_t sb = base + 32768 + s * KV_BYTES;

        // S = Q K^T, 3-term split
        float sc_[8][4];
        #pragma unroll
        for (int nt = 0; nt < 8; nt++)
            #pragma unroll
            for (int c = 0; c < 4; c++) sc_[nt][c] = 0.f;

        #pragma unroll
        for (int ks = 0; ks < 4; ks++) {
            const uint32_t kb = (uint32_t)(ks * 16 + lkof) * 2;
            #pragma unroll
            for (int p = 0; p < 4; p++) {
                uint32_t ro = (uint32_t)(p * 16 + lrow) * 128;
                uint32_t r0, r1, r2, r3, u0, u1, u2, u3;
                ldsm_x4(r0, r1, r2, r3, sb + swz(ro + kb));          // Kh
                ldsm_x4(u0, u1, u2, u3, sb + 8192 + swz(ro + kb));   // Kl
                float* s0 = sc_[2 * p];
                float* s1 = sc_[2 * p + 1];
                mma16816(s0[0], s0[1], s0[2], s0[3], qh[ks][0], qh[ks][1], qh[ks][2], qh[ks][3], r0, r2);
                mma16816(s0[0], s0[1], s0[2], s0[3], qh[ks][0], qh[ks][1], qh[ks][2], qh[ks][3], u0, u2);
                mma16816(s0[0], s0[1], s0[2], s0[3], ql[ks][0], ql[ks][1], ql[ks][2], ql[ks][3], r0, r2);
                mma16816(s1[0], s1[1], s1[2], s1[3], qh[ks][0], qh[ks][1], qh[ks][2], qh[ks][3], r1, r3);
                mma16816(s1[0], s1[1], s1[2], s1[3], qh[ks][0], qh[ks][1], qh[ks][2], qh[ks][3], u1, u3);
                mma16816(s1[0], s1[1], s1[2], s1[3], ql[ks][0], ql[ks][1], ql[ks][2], ql[ks][3], r1, r3);
            }
        }

        if (k0 + 64 > q0) {
            #pragma unroll
            for (int nt = 0; nt < 8; nt++) {
                int col = k0 + nt * 8 + 2 * cq;
                if (col     > row0)     sc_[nt][0] = -INFINITY;
                if (col + 1 > row0)     sc_[nt][1] = -INFINITY;
                if (col     > row0 + 8) sc_[nt][2] = -INFINITY;
                if (col + 1 > row0 + 8) sc_[nt][3] = -INFINITY;
            }
        }

        float mx0 = -INFINITY, mx1 = -INFINITY;
        #pragma unroll
        for (int nt = 0; nt < 8; nt++) {
            mx0 = fmaxf(mx0, fmaxf(sc_[nt][0], sc_[nt][1]));
            mx1 = fmaxf(mx1, fmaxf(sc_[nt][2], sc_[nt][3]));
        }
        mx0 = fmaxf(mx0, __shfl_xor_sync(0xffffffffu, mx0, 1));
        mx0 = fmaxf(mx0, __shfl_xor_sync(0xffffffffu, mx0, 2));
        mx1 = fmaxf(mx1, __shfl_xor_sync(0xffffffffu, mx1, 1));
        mx1 = fmaxf(mx1, __shfl_xor_sync(0xffffffffu, mx1, 2));
        float mn0 = fmaxf(m0, mx0), mn1 = fmaxf(m1, mx1);
        float cf0 = fast_exp2(m0 - mn0), cf1 = fast_exp2(m1 - mn1);
        m0 = mn0; m1 = mn1;
        lp0 *= cf0; lp1 *= cf1;
        #pragma unroll
        for (int dt = 0; dt < 8; dt++) {
            o[dt][0] *= cf0; o[dt][1] *= cf0;
            o[dt][2] *= cf1; o[dt][3] *= cf1;
        }

        uint32_t pah0[8], pah1[8], pal0[8], pal1[8];
        #pragma unroll
        for (int nt = 0; nt < 8; nt++) {
            float p0 = fast_exp2(sc_[nt][0] - m0);
            float p1 = fast_exp2(sc_[nt][1] - m0);
            float p2 = fast_exp2(sc_[nt][2] - m1);
            float p3 = fast_exp2(sc_[nt][3] - m1);
            lp0 += p0 + p1; lp1 += p2 + p3;
            float h0 = __bfloat162float(__float2bfloat16(p0));
            float h1 = __bfloat162float(__float2bfloat16(p1));
            float h2 = __bfloat162float(__float2bfloat16(p2));
            float h3 = __bfloat162float(__float2bfloat16(p3));
            pah0[nt] = pack_bf16x2(h0, h1);
            pah1[nt] = pack_bf16x2(h2, h3);
            pal0[nt] = pack_bf16x2(p0 - h0, p1 - h1);
            pal1[nt] = pack_bf16x2(p2 - h2, p3 - h3);
        }

        // O += P V
        #pragma unroll
        for (int kk = 0; kk < 4; kk++) {
            uint32_t ah0 = pah0[2 * kk], ah1 = pah1[2 * kk];
            uint32_t ah2 = pah0[2 * kk + 1], ah3 = pah1[2 * kk + 1];
            uint32_t al0 = pal0[2 * kk], al1 = pal1[2 * kk];
            uint32_t al2 = pal0[2 * kk + 1], al3 = pal1[2 * kk + 1];
            const uint32_t kb = (uint32_t)(kk * 16 + lkof) * 2;
            #pragma unroll
            for (int dp = 0; dp < 4; dp++) {
                uint32_t ro = (uint32_t)(dp * 16 + lrow) * 128;
                uint32_t v0, v1, v2, v3, x0, x1, x2, x3;
                ldsm_x4(v0, v1, v2, v3, sb + 16384 + swz(ro + kb));  // Vth
                ldsm_x4(x0, x1, x2, x3, sb + 24576 + swz(ro + kb));  // Vtl
                float* oa = o[2 * dp];
                float* ob = o[2 * dp + 1];
                mma16816(oa[0], oa[1], oa[2], oa[3], ah0, ah1, ah2, ah3, v0, v2);
                mma16816(oa[0], oa[1], oa[2], oa[3], ah0, ah1, ah2, ah3, x0, x2);
                mma16816(oa[0], oa[1], oa[2], oa[3], al0, al1, al2, al3, v0, v2);
                mma16816(ob[0], ob[1], ob[2], ob[3], ah0, ah1, ah2, ah3, v1, v3);
                mma16816(ob[0], ob[1], ob[2], ob[3], ah0, ah1, ah2, ah3, x1, x3);
                mma16816(ob[0], ob[1], ob[2], ob[3], al0, al1, al2, al3, v1, v3);
            }
        }
        __syncthreads();                  // all warps done reading stage s
        if (tid == 0 && t + 3 < ntiles) issue_kv(s, t + 3);
        s = (s == 2) ? 0 : s + 1;
    }

    // epilogue: normalize + write chunk-major split directly
    lp0 += __shfl_xor_sync(0xffffffffu, lp0, 1);
    lp0 += __shfl_xor_sync(0xffffffffu, lp0, 2);
    lp1 += __shfl_xor_sync(0xffffffffu, lp1, 1);
    lp1 += __shfl_xor_sync(0xffffffffu, lp1, 2);
    float inv0 = 1.0f / lp0, inv1 = 1.0f / lp1;
    #pragma unroll
    for (int dt = 0; dt < 8; dt++) {
        int col = h * HDIM + dt * 8 + 2 * cq;
        int kc = col >> 5, cin = col & 31;
        float a0 = o[dt][0] * inv0, a1 = o[dt][1] * inv0;
        float b0 = o[dt][2] * inv1, b1 = o[dt][3] * inv1;
        float a0h = __bfloat162float(__float2bfloat16(a0));
        float a1h = __bfloat162float(__float2bfloat16(a1));
        float b0h = __bfloat162float(__float2bfloat16(b0));
        float b1h = __bfloat162float(__float2bfloat16(b1));
        size_t r0b = ((size_t)kc * TT + row0) * 128;
        size_t r1b = ((size_t)kc * TT + row0 + 8) * 128;
        *(uint32_t*)((char*)Ahl + swzs(r0b + (size_t)cin * 2))      = pack_bf16x2(a0h, a1h);
        *(uint32_t*)((char*)Ahl + swzs(r0b + 64 + (size_t)cin * 2)) = pack_bf16x2(a0 - a0h, a1 - a1h);
        *(uint32_t*)((char*)Ahl + swzs(r1b + (size_t)cin * 2))      = pack_bf16x2(b0h, b1h);
        *(uint32_t*)((char*)Ahl + swzs(r1b + 64 + (size_t)cin * 2)) = pack_bf16x2(b0 - b0h, b1 - b1h);
    }
}

// ---------------------------------------------------------------------------
extern "C" void kernel_launch(void* const* d_in, const int* in_sizes, int n_in,
                              void* d_out, int out_size)
{
    const float* x    = (const float*)d_in[0];
    const float* wqkv = (const float*)d_in[1];
    const float* wout = (const float*)d_in[2];
    float* out = (float*)d_out;

    float* qkv;
    __nv_bfloat16 *xhl, *w1hl, *w2hl, *ahl, *qph, *qpl, *kvp;
    cudaGetSymbolAddress((void**)&qkv,  g_qkv);
    cudaGetSymbolAddress((void**)&xhl,  g_xhl);
    cudaGetSymbolAddress((void**)&w1hl, g_w1hl);
    cudaGetSymbolAddress((void**)&w2hl, g_w2hl);
    cudaGetSymbolAddress((void**)&ahl,  g_ahl);
    cudaGetSymbolAddress((void**)&qph,  g_qph);
    cudaGetSymbolAddress((void**)&qpl,  g_qpl);
    cudaGetSymbolAddress((void**)&kvp,  g_kvp);

    cudaFuncSetAttribute(tc_gemm,  cudaFuncAttributeMaxDynamicSharedMemorySize, GSMEM);
    cudaFuncSetAttribute(attn_mma, cudaFuncAttributeMaxDynamicSharedMemorySize, ASMEM);

    // prep
    split_chunk<<<(TT * DD / 8 + 255) / 256, 256>>>(x, xhl, TT, DD);
    wsplit_chunk<<<dim3(3 * DD / 32, DD / 32), dim3(32, 8)>>>(wqkv, w1hl, DD, 3 * DD);
    wsplit_chunk<<<dim3(DD / 32, DD / 32), dim3(32, 8)>>>(wout, w2hl, DD, DD);

    // 1) QKV projection (persistent)
    {
        int total = (TT / 128) * (3 * DD / 128);   // 768
        int grid = total < 296 ? total : 296;
        tc_gemm<<<grid, 256, GSMEM>>>(xhl, w1hl, qkv, TT, 3 * DD, DD);
    }

    // attention operand packing
    kv_pack<<<dim3(TT / 64, NH), 256>>>(qkv, qph, qpl, kvp);

    // 2) causal attention (writes split ahl directly)
    attn_mma<<<dim3(TT / 128, NH), 256, ASMEM>>>(qph, qpl, kvp, ahl);

    // 3) output projection (persistent)
    {
        int total = (TT / 128) * (DD / 128);       // 256
        int grid = total < 296 ? total : 296;
        tc_gemm<<<grid, 256, GSMEM>>>(ahl, w2hl, out, TT, DD, DD);
    }
}